// round 12
// baseline (speedup 1.0000x reference)
#include <cuda_runtime.h>
#include <cuda_bf16.h>
#include <math.h>
#include <stdint.h>

#define BDIM   8192
#define LDIM   512
#define NCODE  8
#define KCODE  1024
#define SDIM   64
#define INV_TAU 14.285714285714286f
#define MSHIFT  14.285714285714286f

// ---- scratch (device globals; no allocation allowed) ----
__device__ float g_zsq[BDIM];
__device__ float g_qsq[BDIM];
__device__ float g_rowsum[BDIM];
__device__ float g_diag[BDIM];
__device__ float g_e2[NCODE * KCODE];
__device__ float g_commit;
__device__ int   g_done;
__device__ __nv_bfloat16 g_qb[(size_t)BDIM * LDIM];    // quant_z bf16
__device__ __nv_bfloat16 g_zb[(size_t)BDIM * LDIM];    // z bf16
__device__ __nv_bfloat16 g_ebh[NCODE * KCODE * SDIM];  // emb hi bf16
__device__ __nv_bfloat16 g_ebl[NCODE * KCODE * SDIM];  // emb lo bf16

// ============================================================
// PTX helpers (base ISA: mma.sync / ldmatrix / cp.async)
// ============================================================
__device__ __forceinline__ uint32_t smem_u32(const void* p) {
    uint32_t a;
    asm("{ .reg .u64 t; cvta.to.shared.u64 t, %1; cvt.u32.u64 %0, t; }" : "=r"(a) : "l"(p));
    return a;
}
__device__ __forceinline__ void ldm4(uint32_t* r, uint32_t addr) {
    asm volatile("ldmatrix.sync.aligned.m8n8.x4.shared.b16 {%0,%1,%2,%3}, [%4];"
        : "=r"(r[0]), "=r"(r[1]), "=r"(r[2]), "=r"(r[3]) : "r"(addr));
}
__device__ __forceinline__ void mma16816(float* c, const uint32_t* a, const uint32_t* b) {
    asm volatile("mma.sync.aligned.m16n8k16.row.col.f32.bf16.bf16.f32 "
        "{%0,%1,%2,%3}, {%4,%5,%6,%7}, {%8,%9}, {%0,%1,%2,%3};"
        : "+f"(c[0]), "+f"(c[1]), "+f"(c[2]), "+f"(c[3])
        : "r"(a[0]), "r"(a[1]), "r"(a[2]), "r"(a[3]), "r"(b[0]), "r"(b[1]));
}
__device__ __forceinline__ void cp16(uint32_t saddr, const void* gaddr) {
    asm volatile("cp.async.cg.shared.global [%0], [%1], 16;" :: "r"(saddr), "l"(gaddr));
}
__device__ __forceinline__ void cp_commit() { asm volatile("cp.async.commit_group;" ::: "memory"); }
__device__ __forceinline__ void cp_wait1()  { asm volatile("cp.async.wait_group 1;" ::: "memory"); }
__device__ __forceinline__ void cp_wait0()  { asm volatile("cp.async.wait_group 0;" ::: "memory"); }

__device__ __forceinline__ uint32_t pk(__nv_bfloat16 a, __nv_bfloat16 b) {
    __nv_bfloat162 t; t.x = a; t.y = b;
    return *reinterpret_cast<uint32_t*>(&t);
}
// pack code index into low 10 mantissa bits of distance (approx key)
__device__ __forceinline__ float pkkey(float d, uint32_t kg) {
    return __uint_as_float((__float_as_uint(d) & 0xFFFFFC00u) | kg);
}

// ============================================================
// k0: zero scratch + e2 + bf16 hi/lo split (4 threads/code)
// ============================================================
__global__ void k0_init(const float* __restrict__ emb) {
    int t = blockIdx.x * blockDim.x + threadIdx.x;     // 32768 threads
    if (t < BDIM) { g_zsq[t] = 0.f; g_qsq[t] = 0.f; g_rowsum[t] = 0.f; }
    if (t == 0) { g_commit = 0.f; g_done = 0; }

    const int code = t >> 2;          // 0..8191
    const int part = t & 3;           // 16 floats each
    const float4* p = (const float4*)(emb + (size_t)code * SDIM + part * 16);
    uint32_t* bh = (uint32_t*)(g_ebh + (size_t)code * SDIM + part * 16);
    uint32_t* bl = (uint32_t*)(g_ebl + (size_t)code * SDIM + part * 16);
    float s = 0.f;
    #pragma unroll
    for (int i = 0; i < 4; i++) {
        float4 v = p[i];
        s += v.x * v.x + v.y * v.y + v.z * v.z + v.w * v.w;
        __nv_bfloat16 hx = __float2bfloat16_rn(v.x), hy = __float2bfloat16_rn(v.y);
        __nv_bfloat16 hz = __float2bfloat16_rn(v.z), hw = __float2bfloat16_rn(v.w);
        bh[2 * i]     = pk(hx, hy);
        bh[2 * i + 1] = pk(hz, hw);
        bl[2 * i]     = pk(__float2bfloat16_rn(v.x - __bfloat162float(hx)),
                           __float2bfloat16_rn(v.y - __bfloat162float(hy)));
        bl[2 * i + 1] = pk(__float2bfloat16_rn(v.z - __bfloat162float(hz)),
                           __float2bfloat16_rn(v.w - __bfloat162float(hw)));
    }
    s += __shfl_xor_sync(0xffffffffu, s, 1);
    s += __shfl_xor_sync(0xffffffffu, s, 2);
    if (part == 0) g_e2[code] = s;
}

// ============================================================
// k1: split-bf16 MMA argmin (branchless top-2 + exact recheck)
//     CTA: 128 b-rows x one n; 8 chunks of 128 codes. (R7 layout)
// ============================================================
#define SM_ZH  0
#define SM_ZL  16384
#define SM_EST 32768          // 2 stages x 32768 (Eh +0, El +16384)
#define SM_E2  98304          // 2 stages x 512
#define SM_MG  99328          // 128 rows x 2 warps x 8B
#define SM_BK  101376         // 128 ints
#define SM_K1  101888

__global__ void __launch_bounds__(256, 2) k1_argmin(
    const float* __restrict__ z, const float* __restrict__ emb,
    float* __restrict__ out)
{
    extern __shared__ __align__(128) char smem[];
    const uint32_t sb = smem_u32(smem);
    const int tid  = threadIdx.x;
    const int lane = tid & 31, wid = tid >> 5;
    const int wm = wid & 3, wn = wid >> 2;
    const int b0 = blockIdx.x * 128;
    const int n  = blockIdx.y;

    uint32_t sOff[4]; int gRow[4], gJ[4];
    #pragma unroll
    for (int i = 0; i < 4; i++) {
        int idv = tid + i * 256;
        int row = idv >> 3, j = idv & 7;
        gRow[i] = row; gJ[i] = j;
        sOff[i] = row * 128 + ((j ^ (row & 7)) << 4);
    }
    const __nv_bfloat16* Ebh = g_ebh + (size_t)n * KCODE * SDIM;
    const __nv_bfloat16* Ebl = g_ebl + (size_t)n * KCODE * SDIM;

    // prologue: stage 0 E tiles + e2
    {
        uint32_t sE = sb + SM_EST;
        #pragma unroll
        for (int i = 0; i < 4; i++) {
            cp16(sE + sOff[i],         Ebh + (size_t)gRow[i] * SDIM + gJ[i] * 8);
            cp16(sE + 16384 + sOff[i], Ebl + (size_t)gRow[i] * SDIM + gJ[i] * 8);
        }
        if (tid < 32) cp16(sb + SM_E2 + tid * 16, g_e2 + n * KCODE + tid * 4);
        cp_commit();
    }

    // build Zh/Zl smem tiles (swizzled) from fp32 z
    #pragma unroll
    for (int i = 0; i < 4; i++) {
        int idv = tid + i * 256;
        int row = idv >> 3, j = idv & 7;
        const float4* zp = (const float4*)(z + (size_t)(b0 + row) * LDIM + n * SDIM + j * 8);
        float4 v0 = zp[0], v1 = zp[1];
        float f[8] = {v0.x, v0.y, v0.z, v0.w, v1.x, v1.y, v1.z, v1.w};
        uint32_t hv[4], lv[4];
        #pragma unroll
        for (int q = 0; q < 4; q++) {
            __nv_bfloat16 h0 = __float2bfloat16_rn(f[2 * q]);
            __nv_bfloat16 h1 = __float2bfloat16_rn(f[2 * q + 1]);
            hv[q] = pk(h0, h1);
            lv[q] = pk(__float2bfloat16_rn(f[2 * q]     - __bfloat162float(h0)),
                       __float2bfloat16_rn(f[2 * q + 1] - __bfloat162float(h1)));
        }
        uint32_t off = row * 128 + ((j ^ (row & 7)) << 4);
        *(uint4*)(smem + SM_ZH + off) = make_uint4(hv[0], hv[1], hv[2], hv[3]);
        *(uint4*)(smem + SM_ZL + off) = make_uint4(lv[0], lv[1], lv[2], lv[3]);
    }

    const int rA  = lane & 15;
    const int hiA = lane >> 4;
    const int rB  = (lane & 7) | ((lane & 16) >> 1);
    const int hiB = (lane >> 3) & 1;
    const int swz = lane & 7;
    const uint32_t aRow0 = (uint32_t)(wm * 32 + rA) * 128;
    const uint32_t bRow0 = (uint32_t)(wn * 64 + rB) * 128;

    // branchless top-2 keys per row slot
    float tv1[4], tv2[4];
    #pragma unroll
    for (int q = 0; q < 4; q++) { tv1[q] = __uint_as_float(0x7F800000u); tv2[q] = tv1[q]; }

    const int g = lane >> 2, tg = lane & 3;

    #pragma unroll
    for (int s = 0; s < 8; s++) {
        cp_wait0();              // stage s ready (distance-1 prefetch)
        __syncthreads();         // all warps done with stage s-1 buffers
        if (s + 1 < 8) {
            uint32_t sE = sb + SM_EST + ((s + 1) & 1) * 32768;
            size_t base = (size_t)(s + 1) * 128 * SDIM;
            #pragma unroll
            for (int i = 0; i < 4; i++) {
                cp16(sE + sOff[i],         Ebh + base + (size_t)gRow[i] * SDIM + gJ[i] * 8);
                cp16(sE + 16384 + sOff[i], Ebl + base + (size_t)gRow[i] * SDIM + gJ[i] * 8);
            }
            if (tid < 32)
                cp16(sb + SM_E2 + ((s + 1) & 1) * 512 + tid * 16,
                     g_e2 + n * KCODE + (s + 1) * 128 + tid * 4);
            cp_commit();
        }

        const uint32_t sEh = sb + SM_EST + (s & 1) * 32768;
        const uint32_t sEl = sEh + 16384;

        float c[2][8][4] = {};
        #pragma unroll
        for (int kk = 0; kk < 4; kk++) {
            const uint32_t gsel  = (((kk << 1) | hiA) ^ swz) << 4;
            const uint32_t gselB = (((kk << 1) | hiB) ^ swz) << 4;
            uint32_t ah[2][4], al[2][4];
            #pragma unroll
            for (int mt = 0; mt < 2; mt++) {
                ldm4(ah[mt], sb + SM_ZH + aRow0 + mt * 2048 + gsel);
                ldm4(al[mt], sb + SM_ZL + aRow0 + mt * 2048 + gsel);
            }
            #pragma unroll
            for (int nt2 = 0; nt2 < 4; nt2++) {
                uint32_t bh[4], bl[4];
                ldm4(bh, sEh + bRow0 + nt2 * 2048 + gselB);
                ldm4(bl, sEl + bRow0 + nt2 * 2048 + gselB);
                #pragma unroll
                for (int mt = 0; mt < 2; mt++) {
                    mma16816(c[mt][2 * nt2],     ah[mt], &bh[0]);
                    mma16816(c[mt][2 * nt2 + 1], ah[mt], &bh[2]);
                    mma16816(c[mt][2 * nt2],     ah[mt], &bl[0]);
                    mma16816(c[mt][2 * nt2 + 1], ah[mt], &bl[2]);
                    mma16816(c[mt][2 * nt2],     al[mt], &bh[0]);
                    mma16816(c[mt][2 * nt2 + 1], al[mt], &bh[2]);
                }
            }
        }

        // branchless top-2 epilogue: dist = e2 - 2*cross, key = dist|idx
        const float* e2s = (const float*)(smem + SM_E2 + (s & 1) * 512);
        #pragma unroll
        for (int nt = 0; nt < 8; nt++) {
            int col = wn * 64 + nt * 8 + tg * 2;
            float2 e2v = *(const float2*)(e2s + col);
            uint32_t kg = (uint32_t)(s * 128 + col);
            #pragma unroll
            for (int mt = 0; mt < 2; mt++)
                #pragma unroll
                for (int h = 0; h < 2; h++) {
                    int q = mt * 2 + h;
                    float k0f = pkkey(fmaf(-2.f, c[mt][nt][h * 2],     e2v.x), kg);
                    float k1f = pkkey(fmaf(-2.f, c[mt][nt][h * 2 + 1], e2v.y), kg + 1);
                    tv2[q] = fminf(tv2[q], fmaxf(tv1[q], k0f));
                    tv1[q] = fminf(tv1[q], k0f);
                    tv2[q] = fminf(tv2[q], fmaxf(tv1[q], k1f));
                    tv1[q] = fminf(tv1[q], k1f);
                }
        }
    }

    // quad merge over tg lanes (pure min/max), stash per (row, wn)
    #pragma unroll
    for (int q = 0; q < 4; q++) {
        #pragma unroll
        for (int off = 1; off <= 2; off <<= 1) {
            float o1 = __shfl_xor_sync(0xffffffffu, tv1[q], off);
            float o2 = __shfl_xor_sync(0xffffffffu, tv2[q], off);
            float n2 = fminf(fminf(tv2[q], o2), fmaxf(tv1[q], o1));
            tv1[q] = fminf(tv1[q], o1);
            tv2[q] = n2;
        }
        if (tg == 0) {
            int mt = q >> 1, h = q & 1;
            int row = wm * 32 + mt * 16 + h * 8 + g;
            ((float2*)(smem + SM_MG))[row * 2 + wn] = make_float2(tv1[q], tv2[q]);
        }
    }
    __syncthreads();

    // exact fp32 recheck of top-2 per row
    int* bk = (int*)(smem + SM_BK);
    if (tid < 128) {
        const float2* mg = (const float2*)(smem + SM_MG);
        float2 a = mg[tid * 2], b = mg[tid * 2 + 1];
        float m1 = fminf(a.x, b.x);
        float m2 = fminf(fmaxf(a.x, b.x), fminf(a.y, b.y));
        int ia = (int)(__float_as_uint(m1) & 1023u);
        int ib = (int)(__float_as_uint(m2) & 1023u);
        const float4* zp = (const float4*)(z + (size_t)(b0 + tid) * LDIM + n * SDIM);
        const float4* ea = (const float4*)(emb + ((size_t)(n * KCODE + ia)) * SDIM);
        const float4* eb = (const float4*)(emb + ((size_t)(n * KCODE + ib)) * SDIM);
        float da = 0.f, db = 0.f;
        #pragma unroll
        for (int i = 0; i < 16; i++) {
            float4 zv = zp[i], va = ea[i], vb = eb[i];
            da += zv.x * va.x + zv.y * va.y + zv.z * va.z + zv.w * va.w;
            db += zv.x * vb.x + zv.y * vb.y + zv.z * vb.z + zv.w * vb.w;
        }
        float dA = g_e2[n * KCODE + ia] - 2.f * da;
        float dB = g_e2[n * KCODE + ib] - 2.f * db;
        int kq = (dA < dB || (dA == dB && ia < ib)) ? ia : ib;
        bk[tid] = kq;
        out[(size_t)BDIM * LDIM + 2 + (size_t)(b0 + tid) * NCODE + n] = (float)kq;
    }
    __syncthreads();

    // gather quant + losses + bf16 copies (2 threads per row, 32 d each)
    {
        const int row   = tid >> 1;
        const int dbase = (tid & 1) * 32;
        const int kq    = bk[row];
        const float4* ep4 = (const float4*)(emb + ((size_t)(n * KCODE + kq)) * SDIM + dbase);
        const float4* zp4 = (const float4*)(z + (size_t)(b0 + row) * LDIM + n * SDIM + dbase);
        float4*       op4 = (float4*)(out + (size_t)(b0 + row) * LDIM + n * SDIM + dbase);
        __nv_bfloat162* qb2 = (__nv_bfloat162*)(g_qb + (size_t)(b0 + row) * LDIM + n * SDIM + dbase);
        __nv_bfloat162* zb2 = (__nv_bfloat162*)(g_zb + (size_t)(b0 + row) * LDIM + n * SDIM + dbase);

        float qs = 0.f, zs = 0.f, cs = 0.f;
        #pragma unroll
        for (int i = 0; i < 8; i++) {
            float4 q4 = ep4[i];
            float4 z4 = zp4[i];
            op4[i] = q4;
            qb2[2 * i]     = __floats2bfloat162_rn(q4.x, q4.y);
            qb2[2 * i + 1] = __floats2bfloat162_rn(q4.z, q4.w);
            zb2[2 * i]     = __floats2bfloat162_rn(z4.x, z4.y);
            zb2[2 * i + 1] = __floats2bfloat162_rn(z4.z, z4.w);
            float d0 = q4.x - z4.x, d1 = q4.y - z4.y, d2 = q4.z - z4.z, d3 = q4.w - z4.w;
            qs += q4.x * q4.x + q4.y * q4.y + q4.z * q4.z + q4.w * q4.w;
            zs += z4.x * z4.x + z4.y * z4.y + z4.z * z4.z + z4.w * z4.w;
            cs += d0 * d0 + d1 * d1 + d2 * d2 + d3 * d3;
        }
        qs += __shfl_xor_sync(0xffffffffu, qs, 1);
        zs += __shfl_xor_sync(0xffffffffu, zs, 1);
        if ((tid & 1) == 0) {
            atomicAdd(&g_qsq[b0 + row], qs);
            atomicAdd(&g_zsq[b0 + row], zs);
        }
        #pragma unroll
        for (int o = 16; o; o >>= 1) cs += __shfl_xor_sync(0xffffffffu, cs, o);
        if ((tid & 31) == 0) atomicAdd(&g_commit, cs);
    }
}

// ============================================================
// k3: bf16 mma.sync GEMM (8192x8192x512) + exp + rowsum + diag
//     R10 double-buffered mainloop (measured best 282.8us).
//     __launch_bounds__(256,2): regs MUST stay <=128 (RF cliff).
//     Last CTA (g_done) computes both output scalars (fused k4).
// ============================================================
#define KS 64
#define STG_BYTES (128 * 128)
#define SM3_IQ   (4 * STG_BYTES)           // 512 B invq tile
#define SM3_IZ   (4 * STG_BYTES + 512)     // 512 B invz tile
#define SM3_TOT  (4 * STG_BYTES + 1024)

__global__ void __launch_bounds__(256, 2) k3_mma(float* __restrict__ out) {
    extern __shared__ __align__(128) char smem[];
    const uint32_t sb = smem_u32(smem);
    const int tid  = threadIdx.x;
    const int lane = tid & 31, wid = tid >> 5;
    const int wm = wid & 3, wn = wid >> 2;
    const int bm0 = blockIdx.y * 128, bn0 = blockIdx.x * 128;
    const __nv_bfloat16* __restrict__ Qb = g_qb;
    const __nv_bfloat16* __restrict__ Zb = g_zb;

    uint32_t sOff[4]; int gRow[4], gJ[4];
    #pragma unroll
    for (int i = 0; i < 4; i++) {
        int idv = tid + i * 256;
        int row = idv >> 3, j = idv & 7;
        gRow[i] = row; gJ[i] = j;
        sOff[i] = row * 128 + ((j ^ (row & 7)) << 4);
    }

    const int rA  = lane & 15;
    const int hiA = lane >> 4;
    const int rB  = (lane & 7) | ((lane & 16) >> 1);
    const int hiB = (lane >> 3) & 1;
    const int swz = lane & 7;
    const uint32_t aRow0 = (uint32_t)(wm * 32 + rA) * 128;
    const uint32_t bRow0 = (uint32_t)(wn * 64 + rB) * 128;

    float c[2][8][4];
    #pragma unroll
    for (int mt = 0; mt < 2; mt++)
        #pragma unroll
        for (int nt = 0; nt < 8; nt++)
            #pragma unroll
            for (int e = 0; e < 4; e++) c[mt][nt][e] = 0.f;

    // fused k2: compute invq (rows) / invz (cols) into smem
    if (tid < 128) {
        float v = g_qsq[bm0 + tid];
        ((float*)(smem + SM3_IQ))[tid] = INV_TAU / fmaxf(sqrtf(v), 1e-12f);
    } else {
        float v = g_zsq[bn0 + tid - 128];
        ((float*)(smem + SM3_IZ))[tid - 128] = 1.f / fmaxf(sqrtf(v), 1e-12f);
    }

    {
        uint32_t sA = sb, sB = sb + STG_BYTES;
        #pragma unroll
        for (int i = 0; i < 4; i++) {
            cp16(sA + sOff[i], Qb + (size_t)(bm0 + gRow[i]) * LDIM + gJ[i] * 8);
            cp16(sB + sOff[i], Zb + (size_t)(bn0 + gRow[i]) * LDIM + gJ[i] * 8);
        }
        cp_commit();
    }

    #pragma unroll
    for (int s = 0; s < 8; s++) {
        if (s < 7) {
            uint32_t sA = sb + ((s + 1) & 1) * (2 * STG_BYTES);
            uint32_t sB = sA + STG_BYTES;
            int kc = (s + 1) * KS;
            #pragma unroll
            for (int i = 0; i < 4; i++) {
                cp16(sA + sOff[i], Qb + (size_t)(bm0 + gRow[i]) * LDIM + kc + gJ[i] * 8);
                cp16(sB + sOff[i], Zb + (size_t)(bn0 + gRow[i]) * LDIM + kc + gJ[i] * 8);
            }
            cp_commit();
            cp_wait1();
        } else {
            cp_wait0();
        }
        __syncthreads();

        const uint32_t sA = sb + (s & 1) * (2 * STG_BYTES);
        const uint32_t sB = sA + STG_BYTES;

        #pragma unroll
        for (int kk = 0; kk < 4; kk++) {
            uint32_t a[2][4];
            #pragma unroll
            for (int mt = 0; mt < 2; mt++)
                ldm4(a[mt], sA + aRow0 + mt * 2048 + ((((kk << 1) | hiA) ^ swz) << 4));
            uint32_t bfr[4][4];
            #pragma unroll
            for (int nt2 = 0; nt2 < 4; nt2++)
                ldm4(bfr[nt2], sB + bRow0 + nt2 * 2048 + ((((kk << 1) | hiB) ^ swz) << 4));
            #pragma unroll
            for (int mt = 0; mt < 2; mt++)
                #pragma unroll
                for (int nt2 = 0; nt2 < 4; nt2++) {
                    mma16816(c[mt][2 * nt2],     a[mt], &bfr[nt2][0]);
                    mma16816(c[mt][2 * nt2 + 1], a[mt], &bfr[nt2][2]);
                }
        }
        __syncthreads();
    }

    const int g = lane >> 2, tg = lane & 3;
    const bool diagblk = (bm0 == bn0);
    const float* iqS = (const float*)(smem + SM3_IQ);
    const float* izS = (const float*)(smem + SM3_IZ);
    int grow[4]; float iq[4], rs[4];
    #pragma unroll
    for (int mt = 0; mt < 2; mt++)
        #pragma unroll
        for (int h = 0; h < 2; h++) {
            int lr = wm * 32 + mt * 16 + h * 8 + g;
            grow[mt * 2 + h] = bm0 + lr;
            iq[mt * 2 + h] = iqS[lr];
            rs[mt * 2 + h] = 0.f;
        }
    #pragma unroll
    for (int nt = 0; nt < 8; nt++) {
        int lcol = wn * 64 + nt * 8 + tg * 2;
        int col  = bn0 + lcol;
        float iz0 = izS[lcol], iz1 = izS[lcol + 1];
        #pragma unroll
        for (int mt = 0; mt < 2; mt++)
            #pragma unroll
            for (int h = 0; h < 2; h++) {
                int q = mt * 2 + h;
                float l0 = c[mt][nt][h * 2 + 0] * iq[q] * iz0;
                float l1 = c[mt][nt][h * 2 + 1] * iq[q] * iz1;
                if (diagblk) {
                    if (grow[q] == col)     g_diag[grow[q]] = l0;
                    if (grow[q] == col + 1) g_diag[grow[q]] = l1;
                }
                rs[q] += __expf(l0 - MSHIFT) + __expf(l1 - MSHIFT);
            }
    }
    #pragma unroll
    for (int q = 0; q < 4; q++) {
        rs[q] += __shfl_xor_sync(0xffffffffu, rs[q], 1);
        rs[q] += __shfl_xor_sync(0xffffffffu, rs[q], 2);
        if (tg == 0) atomicAdd(&g_rowsum[grow[q]], rs[q]);
    }

    // ---- fused k4: last CTA computes both scalars ----
    __threadfence();
    __syncthreads();
    __shared__ int sdone;
    __shared__ float wsum[8];
    if (tid == 0) sdone = (atomicAdd(&g_done, 1) == 4095) ? 1 : 0;
    __syncthreads();
    if (sdone) {
        float s = 0.f;
        for (int b = tid; b < BDIM; b += 256)
            s += MSHIFT + logf(__ldcg(&g_rowsum[b])) - __ldcg(&g_diag[b]);
        #pragma unroll
        for (int o = 16; o; o >>= 1) s += __shfl_xor_sync(0xffffffffu, s, o);
        if ((tid & 31) == 0) wsum[tid >> 5] = s;
        __syncthreads();
        if (tid == 0) {
            float tot = 0.f;
            #pragma unroll
            for (int w = 0; w < 8; w++) tot += wsum[w];
            float com = __ldcg(&g_commit);
            out[(size_t)BDIM * LDIM]     = 2.0f * com / (float)((size_t)BDIM * LDIM);
            out[(size_t)BDIM * LDIM + 1] = tot / (float)BDIM;
        }
    }
}

// ============================================================
extern "C" void kernel_launch(void* const* d_in, const int* in_sizes, int n_in,
                              void* d_out, int out_size)
{
    const float* z   = (const float*)d_in[0];
    const float* emb = (const float*)d_in[1];
    float* out = (float*)d_out;

    cudaFuncSetAttribute(k3_mma, cudaFuncAttributeMaxDynamicSharedMemorySize, SM3_TOT);
    cudaFuncSetAttribute(k1_argmin, cudaFuncAttributeMaxDynamicSharedMemorySize, SM_K1);

    k0_init<<<128, 256>>>(emb);
    dim3 g1(BDIM / 128, NCODE);
    k1_argmin<<<g1, 256, SM_K1>>>(z, emb, out);
    dim3 g3(BDIM / 128, BDIM / 128);
    k3_mma<<<g3, 256, SM3_TOT>>>(out);
}

// round 13
// speedup vs baseline: 1.0230x; 1.0230x over previous
#include <cuda_runtime.h>
#include <cuda_bf16.h>
#include <math.h>
#include <stdint.h>

#define BDIM   8192
#define LDIM   512
#define NCODE  8
#define KCODE  1024
#define SDIM   64
#define INV_TAU 14.285714285714286f
#define MSHIFT  14.285714285714286f

// ---- scratch (device globals; no allocation allowed) ----
__device__ float g_zsq[BDIM];
__device__ float g_qsq[BDIM];
__device__ float g_rowsum[BDIM];
__device__ float g_diag[BDIM];
__device__ float g_e2[NCODE * KCODE];
__device__ float g_commit;
__device__ float g_contrast;
__device__ int   g_done;
__device__ __nv_bfloat16 g_qb[(size_t)BDIM * LDIM];    // quant_z bf16
__device__ __nv_bfloat16 g_zb[(size_t)BDIM * LDIM];    // z bf16
__device__ __nv_bfloat16 g_ebh[NCODE * KCODE * SDIM];  // emb hi bf16
__device__ __nv_bfloat16 g_ebl[NCODE * KCODE * SDIM];  // emb lo bf16

// ============================================================
// PTX helpers (base ISA: mma.sync / ldmatrix / cp.async)
// ============================================================
__device__ __forceinline__ uint32_t smem_u32(const void* p) {
    uint32_t a;
    asm("{ .reg .u64 t; cvta.to.shared.u64 t, %1; cvt.u32.u64 %0, t; }" : "=r"(a) : "l"(p));
    return a;
}
__device__ __forceinline__ void ldm4(uint32_t* r, uint32_t addr) {
    asm volatile("ldmatrix.sync.aligned.m8n8.x4.shared.b16 {%0,%1,%2,%3}, [%4];"
        : "=r"(r[0]), "=r"(r[1]), "=r"(r[2]), "=r"(r[3]) : "r"(addr));
}
__device__ __forceinline__ void mma16816(float* c, const uint32_t* a, const uint32_t* b) {
    asm volatile("mma.sync.aligned.m16n8k16.row.col.f32.bf16.bf16.f32 "
        "{%0,%1,%2,%3}, {%4,%5,%6,%7}, {%8,%9}, {%0,%1,%2,%3};"
        : "+f"(c[0]), "+f"(c[1]), "+f"(c[2]), "+f"(c[3])
        : "r"(a[0]), "r"(a[1]), "r"(a[2]), "r"(a[3]), "r"(b[0]), "r"(b[1]));
}
__device__ __forceinline__ void cp16(uint32_t saddr, const void* gaddr) {
    asm volatile("cp.async.cg.shared.global [%0], [%1], 16;" :: "r"(saddr), "l"(gaddr));
}
__device__ __forceinline__ void cp_commit() { asm volatile("cp.async.commit_group;" ::: "memory"); }
__device__ __forceinline__ void cp_wait1()  { asm volatile("cp.async.wait_group 1;" ::: "memory"); }
__device__ __forceinline__ void cp_wait0()  { asm volatile("cp.async.wait_group 0;" ::: "memory"); }

__device__ __forceinline__ uint32_t pk(__nv_bfloat16 a, __nv_bfloat16 b) {
    __nv_bfloat162 t; t.x = a; t.y = b;
    return *reinterpret_cast<uint32_t*>(&t);
}
// pack code index into low 10 mantissa bits of distance (approx key)
__device__ __forceinline__ float pkkey(float d, uint32_t kg) {
    return __uint_as_float((__float_as_uint(d) & 0xFFFFFC00u) | kg);
}

// ============================================================
// k0: zero scratch + e2 + bf16 hi/lo split (8 threads/code)
// ============================================================
__global__ void k0_init(const float* __restrict__ emb) {
    int t = blockIdx.x * blockDim.x + threadIdx.x;     // 65536 threads
    if (t < BDIM) { g_zsq[t] = 0.f; g_qsq[t] = 0.f; g_rowsum[t] = 0.f; }
    if (t == 0) { g_commit = 0.f; g_contrast = 0.f; g_done = 0; }

    const int code = t >> 3;          // 0..8191
    const int part = t & 7;           // 8 floats each
    const float4* p = (const float4*)(emb + (size_t)code * SDIM + part * 8);
    uint32_t* bh = (uint32_t*)(g_ebh + (size_t)code * SDIM + part * 8);
    uint32_t* bl = (uint32_t*)(g_ebl + (size_t)code * SDIM + part * 8);
    float s = 0.f;
    #pragma unroll
    for (int i = 0; i < 2; i++) {
        float4 v = p[i];
        s += v.x * v.x + v.y * v.y + v.z * v.z + v.w * v.w;
        __nv_bfloat16 hx = __float2bfloat16_rn(v.x), hy = __float2bfloat16_rn(v.y);
        __nv_bfloat16 hz = __float2bfloat16_rn(v.z), hw = __float2bfloat16_rn(v.w);
        bh[2 * i]     = pk(hx, hy);
        bh[2 * i + 1] = pk(hz, hw);
        bl[2 * i]     = pk(__float2bfloat16_rn(v.x - __bfloat162float(hx)),
                           __float2bfloat16_rn(v.y - __bfloat162float(hy)));
        bl[2 * i + 1] = pk(__float2bfloat16_rn(v.z - __bfloat162float(hz)),
                           __float2bfloat16_rn(v.w - __bfloat162float(hw)));
    }
    s += __shfl_xor_sync(0xffffffffu, s, 1);
    s += __shfl_xor_sync(0xffffffffu, s, 2);
    s += __shfl_xor_sync(0xffffffffu, s, 4);
    if (part == 0) g_e2[code] = s;
}

// ============================================================
// k1: split-bf16 MMA argmin (branchless top-2 + exact recheck)
//     CTA: 128 b-rows x one n; 8 chunks of 128 codes. (R7 layout)
// ============================================================
#define SM_ZH  0
#define SM_ZL  16384
#define SM_EST 32768          // 2 stages x 32768 (Eh +0, El +16384)
#define SM_E2  98304          // 2 stages x 512
#define SM_MG  99328          // 128 rows x 2 warps x 8B
#define SM_BK  101376         // 128 ints
#define SM_K1  101888

__global__ void __launch_bounds__(256, 2) k1_argmin(
    const float* __restrict__ z, const float* __restrict__ emb,
    float* __restrict__ out)
{
    extern __shared__ __align__(128) char smem[];
    const uint32_t sb = smem_u32(smem);
    const int tid  = threadIdx.x;
    const int lane = tid & 31, wid = tid >> 5;
    const int wm = wid & 3, wn = wid >> 2;
    const int b0 = blockIdx.x * 128;
    const int n  = blockIdx.y;

    uint32_t sOff[4]; int gRow[4], gJ[4];
    #pragma unroll
    for (int i = 0; i < 4; i++) {
        int idv = tid + i * 256;
        int row = idv >> 3, j = idv & 7;
        gRow[i] = row; gJ[i] = j;
        sOff[i] = row * 128 + ((j ^ (row & 7)) << 4);
    }
    const __nv_bfloat16* Ebh = g_ebh + (size_t)n * KCODE * SDIM;
    const __nv_bfloat16* Ebl = g_ebl + (size_t)n * KCODE * SDIM;

    // prologue: stage 0 E tiles + e2
    {
        uint32_t sE = sb + SM_EST;
        #pragma unroll
        for (int i = 0; i < 4; i++) {
            cp16(sE + sOff[i],         Ebh + (size_t)gRow[i] * SDIM + gJ[i] * 8);
            cp16(sE + 16384 + sOff[i], Ebl + (size_t)gRow[i] * SDIM + gJ[i] * 8);
        }
        if (tid < 32) cp16(sb + SM_E2 + tid * 16, g_e2 + n * KCODE + tid * 4);
        cp_commit();
    }

    // build Zh/Zl smem tiles (swizzled) from fp32 z
    #pragma unroll
    for (int i = 0; i < 4; i++) {
        int idv = tid + i * 256;
        int row = idv >> 3, j = idv & 7;
        const float4* zp = (const float4*)(z + (size_t)(b0 + row) * LDIM + n * SDIM + j * 8);
        float4 v0 = zp[0], v1 = zp[1];
        float f[8] = {v0.x, v0.y, v0.z, v0.w, v1.x, v1.y, v1.z, v1.w};
        uint32_t hv[4], lv[4];
        #pragma unroll
        for (int q = 0; q < 4; q++) {
            __nv_bfloat16 h0 = __float2bfloat16_rn(f[2 * q]);
            __nv_bfloat16 h1 = __float2bfloat16_rn(f[2 * q + 1]);
            hv[q] = pk(h0, h1);
            lv[q] = pk(__float2bfloat16_rn(f[2 * q]     - __bfloat162float(h0)),
                       __float2bfloat16_rn(f[2 * q + 1] - __bfloat162float(h1)));
        }
        uint32_t off = row * 128 + ((j ^ (row & 7)) << 4);
        *(uint4*)(smem + SM_ZH + off) = make_uint4(hv[0], hv[1], hv[2], hv[3]);
        *(uint4*)(smem + SM_ZL + off) = make_uint4(lv[0], lv[1], lv[2], lv[3]);
    }

    const int rA  = lane & 15;
    const int hiA = lane >> 4;
    const int rB  = (lane & 7) | ((lane & 16) >> 1);
    const int hiB = (lane >> 3) & 1;
    const int swz = lane & 7;
    const uint32_t aRow0 = (uint32_t)(wm * 32 + rA) * 128;
    const uint32_t bRow0 = (uint32_t)(wn * 64 + rB) * 128;

    // branchless top-2 keys per row slot
    float tv1[4], tv2[4];
    #pragma unroll
    for (int q = 0; q < 4; q++) { tv1[q] = __uint_as_float(0x7F800000u); tv2[q] = tv1[q]; }

    const int g = lane >> 2, tg = lane & 3;

    #pragma unroll
    for (int s = 0; s < 8; s++) {
        cp_wait0();              // stage s ready (distance-1 prefetch)
        __syncthreads();         // all warps done with stage s-1 buffers
        if (s + 1 < 8) {
            uint32_t sE = sb + SM_EST + ((s + 1) & 1) * 32768;
            size_t base = (size_t)(s + 1) * 128 * SDIM;
            #pragma unroll
            for (int i = 0; i < 4; i++) {
                cp16(sE + sOff[i],         Ebh + base + (size_t)gRow[i] * SDIM + gJ[i] * 8);
                cp16(sE + 16384 + sOff[i], Ebl + base + (size_t)gRow[i] * SDIM + gJ[i] * 8);
            }
            if (tid < 32)
                cp16(sb + SM_E2 + ((s + 1) & 1) * 512 + tid * 16,
                     g_e2 + n * KCODE + (s + 1) * 128 + tid * 4);
            cp_commit();
        }

        const uint32_t sEh = sb + SM_EST + (s & 1) * 32768;
        const uint32_t sEl = sEh + 16384;

        float c[2][8][4] = {};
        #pragma unroll
        for (int kk = 0; kk < 4; kk++) {
            const uint32_t gsel  = (((kk << 1) | hiA) ^ swz) << 4;
            const uint32_t gselB = (((kk << 1) | hiB) ^ swz) << 4;
            uint32_t ah[2][4], al[2][4];
            #pragma unroll
            for (int mt = 0; mt < 2; mt++) {
                ldm4(ah[mt], sb + SM_ZH + aRow0 + mt * 2048 + gsel);
                ldm4(al[mt], sb + SM_ZL + aRow0 + mt * 2048 + gsel);
            }
            #pragma unroll
            for (int nt2 = 0; nt2 < 4; nt2++) {
                uint32_t bh[4], bl[4];
                ldm4(bh, sEh + bRow0 + nt2 * 2048 + gselB);
                ldm4(bl, sEl + bRow0 + nt2 * 2048 + gselB);
                #pragma unroll
                for (int mt = 0; mt < 2; mt++) {
                    mma16816(c[mt][2 * nt2],     ah[mt], &bh[0]);
                    mma16816(c[mt][2 * nt2 + 1], ah[mt], &bh[2]);
                    mma16816(c[mt][2 * nt2],     ah[mt], &bl[0]);
                    mma16816(c[mt][2 * nt2 + 1], ah[mt], &bl[2]);
                    mma16816(c[mt][2 * nt2],     al[mt], &bh[0]);
                    mma16816(c[mt][2 * nt2 + 1], al[mt], &bh[2]);
                }
            }
        }

        // branchless top-2 epilogue: dist = e2 - 2*cross, key = dist|idx
        const float* e2s = (const float*)(smem + SM_E2 + (s & 1) * 512);
        #pragma unroll
        for (int nt = 0; nt < 8; nt++) {
            int col = wn * 64 + nt * 8 + tg * 2;
            float2 e2v = *(const float2*)(e2s + col);
            uint32_t kg = (uint32_t)(s * 128 + col);
            #pragma unroll
            for (int mt = 0; mt < 2; mt++)
                #pragma unroll
                for (int h = 0; h < 2; h++) {
                    int q = mt * 2 + h;
                    float k0f = pkkey(fmaf(-2.f, c[mt][nt][h * 2],     e2v.x), kg);
                    float k1f = pkkey(fmaf(-2.f, c[mt][nt][h * 2 + 1], e2v.y), kg + 1);
                    tv2[q] = fminf(tv2[q], fmaxf(tv1[q], k0f));
                    tv1[q] = fminf(tv1[q], k0f);
                    tv2[q] = fminf(tv2[q], fmaxf(tv1[q], k1f));
                    tv1[q] = fminf(tv1[q], k1f);
                }
        }
    }

    // quad merge over tg lanes (pure min/max), stash per (row, wn)
    #pragma unroll
    for (int q = 0; q < 4; q++) {
        #pragma unroll
        for (int off = 1; off <= 2; off <<= 1) {
            float o1 = __shfl_xor_sync(0xffffffffu, tv1[q], off);
            float o2 = __shfl_xor_sync(0xffffffffu, tv2[q], off);
            float n2 = fminf(fminf(tv2[q], o2), fmaxf(tv1[q], o1));
            tv1[q] = fminf(tv1[q], o1);
            tv2[q] = n2;
        }
        if (tg == 0) {
            int mt = q >> 1, h = q & 1;
            int row = wm * 32 + mt * 16 + h * 8 + g;
            ((float2*)(smem + SM_MG))[row * 2 + wn] = make_float2(tv1[q], tv2[q]);
        }
    }
    __syncthreads();

    // exact fp32 recheck of top-2 per row
    int* bk = (int*)(smem + SM_BK);
    if (tid < 128) {
        const float2* mg = (const float2*)(smem + SM_MG);
        float2 a = mg[tid * 2], b = mg[tid * 2 + 1];
        float m1 = fminf(a.x, b.x);
        float m2 = fminf(fmaxf(a.x, b.x), fminf(a.y, b.y));
        int ia = (int)(__float_as_uint(m1) & 1023u);
        int ib = (int)(__float_as_uint(m2) & 1023u);
        const float4* zp = (const float4*)(z + (size_t)(b0 + tid) * LDIM + n * SDIM);
        const float4* ea = (const float4*)(emb + ((size_t)(n * KCODE + ia)) * SDIM);
        const float4* eb = (const float4*)(emb + ((size_t)(n * KCODE + ib)) * SDIM);
        float da = 0.f, db = 0.f;
        #pragma unroll
        for (int i = 0; i < 16; i++) {
            float4 zv = zp[i], va = ea[i], vb = eb[i];
            da += zv.x * va.x + zv.y * va.y + zv.z * va.z + zv.w * va.w;
            db += zv.x * vb.x + zv.y * vb.y + zv.z * vb.z + zv.w * vb.w;
        }
        float dA = g_e2[n * KCODE + ia] - 2.f * da;
        float dB = g_e2[n * KCODE + ib] - 2.f * db;
        int kq = (dA < dB || (dA == dB && ia < ib)) ? ia : ib;
        bk[tid] = kq;
        out[(size_t)BDIM * LDIM + 2 + (size_t)(b0 + tid) * NCODE + n] = (float)kq;
    }
    __syncthreads();

    // gather quant + losses + bf16 copies (2 threads per row, 32 d each)
    {
        const int row   = tid >> 1;
        const int dbase = (tid & 1) * 32;
        const int kq    = bk[row];
        const float4* ep4 = (const float4*)(emb + ((size_t)(n * KCODE + kq)) * SDIM + dbase);
        const float4* zp4 = (const float4*)(z + (size_t)(b0 + row) * LDIM + n * SDIM + dbase);
        float4*       op4 = (float4*)(out + (size_t)(b0 + row) * LDIM + n * SDIM + dbase);
        __nv_bfloat162* qb2 = (__nv_bfloat162*)(g_qb + (size_t)(b0 + row) * LDIM + n * SDIM + dbase);
        __nv_bfloat162* zb2 = (__nv_bfloat162*)(g_zb + (size_t)(b0 + row) * LDIM + n * SDIM + dbase);

        float qs = 0.f, zs = 0.f, cs = 0.f;
        #pragma unroll
        for (int i = 0; i < 8; i++) {
            float4 q4 = ep4[i];
            float4 z4 = zp4[i];
            op4[i] = q4;
            qb2[2 * i]     = __floats2bfloat162_rn(q4.x, q4.y);
            qb2[2 * i + 1] = __floats2bfloat162_rn(q4.z, q4.w);
            zb2[2 * i]     = __floats2bfloat162_rn(z4.x, z4.y);
            zb2[2 * i + 1] = __floats2bfloat162_rn(z4.z, z4.w);
            float d0 = q4.x - z4.x, d1 = q4.y - z4.y, d2 = q4.z - z4.z, d3 = q4.w - z4.w;
            qs += q4.x * q4.x + q4.y * q4.y + q4.z * q4.z + q4.w * q4.w;
            zs += z4.x * z4.x + z4.y * z4.y + z4.z * z4.z + z4.w * z4.w;
            cs += d0 * d0 + d1 * d1 + d2 * d2 + d3 * d3;
        }
        qs += __shfl_xor_sync(0xffffffffu, qs, 1);
        zs += __shfl_xor_sync(0xffffffffu, zs, 1);
        if ((tid & 1) == 0) {
            atomicAdd(&g_qsq[b0 + row], qs);
            atomicAdd(&g_zsq[b0 + row], zs);
        }
        #pragma unroll
        for (int o = 16; o; o >>= 1) cs += __shfl_xor_sync(0xffffffffu, cs, o);
        if ((tid & 31) == 0) atomicAdd(&g_commit, cs);
    }
}

// ============================================================
// k3: bf16 mma.sync GEMM (8192x8192x512) + exp + rowsum + diag
//     R10 double-buffered mainloop (measured best 282.8us).
//     __launch_bounds__(256,2): regs MUST stay <=128 (RF cliff).
// ============================================================
#define KS 64
#define STG_BYTES (128 * 128)
#define SM3_IQ   (4 * STG_BYTES)           // 512 B invq tile
#define SM3_IZ   (4 * STG_BYTES + 512)     // 512 B invz tile
#define SM3_TOT  (4 * STG_BYTES + 1024)

__global__ void __launch_bounds__(256, 2) k3_mma() {
    extern __shared__ __align__(128) char smem[];
    const uint32_t sb = smem_u32(smem);
    const int tid  = threadIdx.x;
    const int lane = tid & 31, wid = tid >> 5;
    const int wm = wid & 3, wn = wid >> 2;
    const int bm0 = blockIdx.y * 128, bn0 = blockIdx.x * 128;
    const __nv_bfloat16* __restrict__ Qb = g_qb;
    const __nv_bfloat16* __restrict__ Zb = g_zb;

    uint32_t sOff[4]; int gRow[4], gJ[4];
    #pragma unroll
    for (int i = 0; i < 4; i++) {
        int idv = tid + i * 256;
        int row = idv >> 3, j = idv & 7;
        gRow[i] = row; gJ[i] = j;
        sOff[i] = row * 128 + ((j ^ (row & 7)) << 4);
    }

    const int rA  = lane & 15;
    const int hiA = lane >> 4;
    const int rB  = (lane & 7) | ((lane & 16) >> 1);
    const int hiB = (lane >> 3) & 1;
    const int swz = lane & 7;
    const uint32_t aRow0 = (uint32_t)(wm * 32 + rA) * 128;
    const uint32_t bRow0 = (uint32_t)(wn * 64 + rB) * 128;

    float c[2][8][4];
    #pragma unroll
    for (int mt = 0; mt < 2; mt++)
        #pragma unroll
        for (int nt = 0; nt < 8; nt++)
            #pragma unroll
            for (int e = 0; e < 4; e++) c[mt][nt][e] = 0.f;

    // fused k2: compute invq (rows) / invz (cols) into smem
    if (tid < 128) {
        float v = g_qsq[bm0 + tid];
        ((float*)(smem + SM3_IQ))[tid] = INV_TAU / fmaxf(sqrtf(v), 1e-12f);
    } else {
        float v = g_zsq[bn0 + tid - 128];
        ((float*)(smem + SM3_IZ))[tid - 128] = 1.f / fmaxf(sqrtf(v), 1e-12f);
    }

    {
        uint32_t sA = sb, sB = sb + STG_BYTES;
        #pragma unroll
        for (int i = 0; i < 4; i++) {
            cp16(sA + sOff[i], Qb + (size_t)(bm0 + gRow[i]) * LDIM + gJ[i] * 8);
            cp16(sB + sOff[i], Zb + (size_t)(bn0 + gRow[i]) * LDIM + gJ[i] * 8);
        }
        cp_commit();
    }

    #pragma unroll
    for (int s = 0; s < 8; s++) {
        if (s < 7) {
            uint32_t sA = sb + ((s + 1) & 1) * (2 * STG_BYTES);
            uint32_t sB = sA + STG_BYTES;
            int kc = (s + 1) * KS;
            #pragma unroll
            for (int i = 0; i < 4; i++) {
                cp16(sA + sOff[i], Qb + (size_t)(bm0 + gRow[i]) * LDIM + kc + gJ[i] * 8);
                cp16(sB + sOff[i], Zb + (size_t)(bn0 + gRow[i]) * LDIM + kc + gJ[i] * 8);
            }
            cp_commit();
            cp_wait1();
        } else {
            cp_wait0();
        }
        __syncthreads();

        const uint32_t sA = sb + (s & 1) * (2 * STG_BYTES);
        const uint32_t sB = sA + STG_BYTES;

        #pragma unroll
        for (int kk = 0; kk < 4; kk++) {
            uint32_t a[2][4];
            #pragma unroll
            for (int mt = 0; mt < 2; mt++)
                ldm4(a[mt], sA + aRow0 + mt * 2048 + ((((kk << 1) | hiA) ^ swz) << 4));
            uint32_t bfr[4][4];
            #pragma unroll
            for (int nt2 = 0; nt2 < 4; nt2++)
                ldm4(bfr[nt2], sB + bRow0 + nt2 * 2048 + ((((kk << 1) | hiB) ^ swz) << 4));
            #pragma unroll
            for (int mt = 0; mt < 2; mt++)
                #pragma unroll
                for (int nt2 = 0; nt2 < 4; nt2++) {
                    mma16816(c[mt][2 * nt2],     a[mt], &bfr[nt2][0]);
                    mma16816(c[mt][2 * nt2 + 1], a[mt], &bfr[nt2][2]);
                }
        }
        __syncthreads();
    }

    const int g = lane >> 2, tg = lane & 3;
    const bool diagblk = (bm0 == bn0);
    const float* iqS = (const float*)(smem + SM3_IQ);
    const float* izS = (const float*)(smem + SM3_IZ);
    int grow[4]; float iq[4], rs[4];
    #pragma unroll
    for (int mt = 0; mt < 2; mt++)
        #pragma unroll
        for (int h = 0; h < 2; h++) {
            int lr = wm * 32 + mt * 16 + h * 8 + g;
            grow[mt * 2 + h] = bm0 + lr;
            iq[mt * 2 + h] = iqS[lr];
            rs[mt * 2 + h] = 0.f;
        }
    #pragma unroll
    for (int nt = 0; nt < 8; nt++) {
        int lcol = wn * 64 + nt * 8 + tg * 2;
        int col  = bn0 + lcol;
        float iz0 = izS[lcol], iz1 = izS[lcol + 1];
        #pragma unroll
        for (int mt = 0; mt < 2; mt++)
            #pragma unroll
            for (int h = 0; h < 2; h++) {
                int q = mt * 2 + h;
                float l0 = c[mt][nt][h * 2 + 0] * iq[q] * iz0;
                float l1 = c[mt][nt][h * 2 + 1] * iq[q] * iz1;
                if (diagblk) {
                    if (grow[q] == col)     g_diag[grow[q]] = l0;
                    if (grow[q] == col + 1) g_diag[grow[q]] = l1;
                }
                rs[q] += __expf(l0 - MSHIFT) + __expf(l1 - MSHIFT);
            }
    }
    #pragma unroll
    for (int q = 0; q < 4; q++) {
        rs[q] += __shfl_xor_sync(0xffffffffu, rs[q], 1);
        rs[q] += __shfl_xor_sync(0xffffffffu, rs[q], 2);
        if (tg == 0) atomicAdd(&g_rowsum[grow[q]], rs[q]);
    }
}

// ============================================================
// k4: contrastive reduction + last-arriver writes scalars
// ============================================================
__global__ void k4_reduce(float* __restrict__ out) {
    int t = blockIdx.x * 256 + threadIdx.x;
    float s = MSHIFT + logf(g_rowsum[t]) - g_diag[t];
    #pragma unroll
    for (int o = 16; o; o >>= 1) s += __shfl_xor_sync(0xffffffffu, s, o);
    if ((threadIdx.x & 31) == 0) {
        atomicAdd(&g_contrast, s);
        __threadfence();
        int v = atomicAdd(&g_done, 1);
        if (v == 255) {                       // 32 blocks x 8 warps
            float con = atomicAdd(&g_contrast, 0.f);
            float com = atomicAdd(&g_commit, 0.f);
            out[(size_t)BDIM * LDIM]     = 2.0f * com / (float)((size_t)BDIM * LDIM);
            out[(size_t)BDIM * LDIM + 1] = con / (float)BDIM;
        }
    }
}

// ============================================================
extern "C" void kernel_launch(void* const* d_in, const int* in_sizes, int n_in,
                              void* d_out, int out_size)
{
    const float* z   = (const float*)d_in[0];
    const float* emb = (const float*)d_in[1];
    float* out = (float*)d_out;

    cudaFuncSetAttribute(k3_mma, cudaFuncAttributeMaxDynamicSharedMemorySize, SM3_TOT);
    cudaFuncSetAttribute(k1_argmin, cudaFuncAttributeMaxDynamicSharedMemorySize, SM_K1);

    k0_init<<<256, 256>>>(emb);
    dim3 g1(BDIM / 128, NCODE);
    k1_argmin<<<g1, 256, SM_K1>>>(z, emb, out);
    dim3 g3(BDIM / 128, BDIM / 128);
    k3_mma<<<g3, 256, SM3_TOT>>>();
    k4_reduce<<<32, 256>>>(out);
}

// round 14
// speedup vs baseline: 1.1310x; 1.1055x over previous
#include <cuda_runtime.h>
#include <cuda_bf16.h>
#include <math.h>
#include <stdint.h>

#define BDIM   8192
#define LDIM   512
#define NCODE  8
#define KCODE  1024
#define SDIM   64
#define INV_TAU 14.285714285714286f
#define MSHIFT  14.285714285714286f

// ---- scratch (device globals; no allocation allowed) ----
__device__ float g_zsq[BDIM];
__device__ float g_qsq[BDIM];
__device__ float g_rowsum[BDIM];
__device__ float g_diag[BDIM];
__device__ float g_e2[NCODE * KCODE];
__device__ float g_commit;
__device__ float g_contrast;
__device__ int   g_done;
__device__ __nv_bfloat16 g_qb[(size_t)BDIM * LDIM];    // quant_z bf16
__device__ __nv_bfloat16 g_zb[(size_t)BDIM * LDIM];    // z bf16
__device__ __nv_bfloat16 g_ebh[NCODE * KCODE * SDIM];  // emb hi bf16

// ============================================================
// PTX helpers (base ISA: mma.sync / ldmatrix / cp.async)
// ============================================================
__device__ __forceinline__ uint32_t smem_u32(const void* p) {
    uint32_t a;
    asm("{ .reg .u64 t; cvta.to.shared.u64 t, %1; cvt.u32.u64 %0, t; }" : "=r"(a) : "l"(p));
    return a;
}
__device__ __forceinline__ void ldm4(uint32_t* r, uint32_t addr) {
    asm volatile("ldmatrix.sync.aligned.m8n8.x4.shared.b16 {%0,%1,%2,%3}, [%4];"
        : "=r"(r[0]), "=r"(r[1]), "=r"(r[2]), "=r"(r[3]) : "r"(addr));
}
__device__ __forceinline__ void mma16816(float* c, const uint32_t* a, const uint32_t* b) {
    asm volatile("mma.sync.aligned.m16n8k16.row.col.f32.bf16.bf16.f32 "
        "{%0,%1,%2,%3}, {%4,%5,%6,%7}, {%8,%9}, {%0,%1,%2,%3};"
        : "+f"(c[0]), "+f"(c[1]), "+f"(c[2]), "+f"(c[3])
        : "r"(a[0]), "r"(a[1]), "r"(a[2]), "r"(a[3]), "r"(b[0]), "r"(b[1]));
}
__device__ __forceinline__ void cp16(uint32_t saddr, const void* gaddr) {
    asm volatile("cp.async.cg.shared.global [%0], [%1], 16;" :: "r"(saddr), "l"(gaddr));
}
__device__ __forceinline__ void cp_commit() { asm volatile("cp.async.commit_group;" ::: "memory"); }
__device__ __forceinline__ void cp_wait1()  { asm volatile("cp.async.wait_group 1;" ::: "memory"); }
__device__ __forceinline__ void cp_wait0()  { asm volatile("cp.async.wait_group 0;" ::: "memory"); }

__device__ __forceinline__ uint32_t pk(__nv_bfloat16 a, __nv_bfloat16 b) {
    __nv_bfloat162 t; t.x = a; t.y = b;
    return *reinterpret_cast<uint32_t*>(&t);
}
// pack code index into low 10 mantissa bits of distance (approx key)
__device__ __forceinline__ float pkkey(float d, uint32_t kg) {
    return __uint_as_float((__float_as_uint(d) & 0xFFFFFC00u) | kg);
}

// ============================================================
// k0: zero scratch + e2 + bf16 hi split of embeddings
// ============================================================
__global__ void k0_init(const float* __restrict__ emb) {
    int t = blockIdx.x * blockDim.x + threadIdx.x;     // 65536 threads
    if (t < BDIM) { g_zsq[t] = 0.f; g_qsq[t] = 0.f; g_rowsum[t] = 0.f; }
    if (t == 0) { g_commit = 0.f; g_contrast = 0.f; g_done = 0; }

    const int code = t >> 3;          // 0..8191
    const int part = t & 7;           // 8 floats each
    const float4* p = (const float4*)(emb + (size_t)code * SDIM + part * 8);
    uint32_t* bh = (uint32_t*)(g_ebh + (size_t)code * SDIM + part * 8);
    float s = 0.f;
    #pragma unroll
    for (int i = 0; i < 2; i++) {
        float4 v = p[i];
        s += v.x * v.x + v.y * v.y + v.z * v.z + v.w * v.w;
        bh[2 * i]     = pk(__float2bfloat16_rn(v.x), __float2bfloat16_rn(v.y));
        bh[2 * i + 1] = pk(__float2bfloat16_rn(v.z), __float2bfloat16_rn(v.w));
    }
    s += __shfl_xor_sync(0xffffffffu, s, 1);
    s += __shfl_xor_sync(0xffffffffu, s, 2);
    s += __shfl_xor_sync(0xffffffffu, s, 4);
    if (part == 0) g_e2[code] = s;
}

// ============================================================
// k1: 2-term split-bf16 MMA argmin (z ~ zh+zl exactly, e ~ eh):
//     cross ~ zh*eh + zl*eh.  dist err sigma ~1.8e-2 << gap ~8.
//     Branchless sorted top-3 + exact fp32 recheck of 3 cands.
// ============================================================
#define SM_ZH  0
#define SM_ZL  16384
#define SM_EST 32768          // 2 stages x 16384 (Eh only)
#define SM_E2  65536          // 2 stages x 512
#define SM_MG  66560          // 128 rows x 2 warps x 16B
#define SM_BK  70656          // 128 ints
#define SM_K1  71168

__global__ void __launch_bounds__(256, 2) k1_argmin(
    const float* __restrict__ z, const float* __restrict__ emb,
    float* __restrict__ out)
{
    extern __shared__ __align__(128) char smem[];
    const uint32_t sb = smem_u32(smem);
    const int tid  = threadIdx.x;
    const int lane = tid & 31, wid = tid >> 5;
    const int wm = wid & 3, wn = wid >> 2;
    const int b0 = blockIdx.x * 128;
    const int n  = blockIdx.y;

    uint32_t sOff[4]; int gRow[4], gJ[4];
    #pragma unroll
    for (int i = 0; i < 4; i++) {
        int idv = tid + i * 256;
        int row = idv >> 3, j = idv & 7;
        gRow[i] = row; gJ[i] = j;
        sOff[i] = row * 128 + ((j ^ (row & 7)) << 4);
    }
    const __nv_bfloat16* Ebh = g_ebh + (size_t)n * KCODE * SDIM;

    // prologue: stage 0 E tile + e2
    {
        uint32_t sE = sb + SM_EST;
        #pragma unroll
        for (int i = 0; i < 4; i++)
            cp16(sE + sOff[i], Ebh + (size_t)gRow[i] * SDIM + gJ[i] * 8);
        if (tid < 32) cp16(sb + SM_E2 + tid * 16, g_e2 + n * KCODE + tid * 4);
        cp_commit();
    }

    // build Zh/Zl smem tiles (swizzled) from fp32 z
    #pragma unroll
    for (int i = 0; i < 4; i++) {
        int idv = tid + i * 256;
        int row = idv >> 3, j = idv & 7;
        const float4* zp = (const float4*)(z + (size_t)(b0 + row) * LDIM + n * SDIM + j * 8);
        float4 v0 = zp[0], v1 = zp[1];
        float f[8] = {v0.x, v0.y, v0.z, v0.w, v1.x, v1.y, v1.z, v1.w};
        uint32_t hv[4], lv[4];
        #pragma unroll
        for (int q = 0; q < 4; q++) {
            __nv_bfloat16 h0 = __float2bfloat16_rn(f[2 * q]);
            __nv_bfloat16 h1 = __float2bfloat16_rn(f[2 * q + 1]);
            hv[q] = pk(h0, h1);
            lv[q] = pk(__float2bfloat16_rn(f[2 * q]     - __bfloat162float(h0)),
                       __float2bfloat16_rn(f[2 * q + 1] - __bfloat162float(h1)));
        }
        uint32_t off = row * 128 + ((j ^ (row & 7)) << 4);
        *(uint4*)(smem + SM_ZH + off) = make_uint4(hv[0], hv[1], hv[2], hv[3]);
        *(uint4*)(smem + SM_ZL + off) = make_uint4(lv[0], lv[1], lv[2], lv[3]);
    }

    const int rA  = lane & 15;
    const int hiA = lane >> 4;
    const int rB  = (lane & 7) | ((lane & 16) >> 1);
    const int hiB = (lane >> 3) & 1;
    const int swz = lane & 7;
    const uint32_t aRow0 = (uint32_t)(wm * 32 + rA) * 128;
    const uint32_t bRow0 = (uint32_t)(wn * 64 + rB) * 128;

    // branchless sorted top-3 keys per row slot
    float tv1[4], tv2[4], tv3[4];
    #pragma unroll
    for (int q = 0; q < 4; q++) {
        tv1[q] = __uint_as_float(0x7F800000u);
        tv2[q] = tv1[q]; tv3[q] = tv1[q];
    }

    const int g = lane >> 2, tg = lane & 3;

    #pragma unroll
    for (int s = 0; s < 8; s++) {
        cp_wait0();              // stage s ready (distance-1 prefetch)
        __syncthreads();         // all warps done with stage s-1 buffers
        if (s + 1 < 8) {
            uint32_t sE = sb + SM_EST + ((s + 1) & 1) * 16384;
            size_t base = (size_t)(s + 1) * 128 * SDIM;
            #pragma unroll
            for (int i = 0; i < 4; i++)
                cp16(sE + sOff[i], Ebh + base + (size_t)gRow[i] * SDIM + gJ[i] * 8);
            if (tid < 32)
                cp16(sb + SM_E2 + ((s + 1) & 1) * 512 + tid * 16,
                     g_e2 + n * KCODE + (s + 1) * 128 + tid * 4);
            cp_commit();
        }

        const uint32_t sEh = sb + SM_EST + (s & 1) * 16384;

        float c[2][8][4] = {};
        #pragma unroll
        for (int kk = 0; kk < 4; kk++) {
            const uint32_t gsel  = (((kk << 1) | hiA) ^ swz) << 4;
            const uint32_t gselB = (((kk << 1) | hiB) ^ swz) << 4;
            uint32_t ah[2][4], al[2][4];
            #pragma unroll
            for (int mt = 0; mt < 2; mt++) {
                ldm4(ah[mt], sb + SM_ZH + aRow0 + mt * 2048 + gsel);
                ldm4(al[mt], sb + SM_ZL + aRow0 + mt * 2048 + gsel);
            }
            #pragma unroll
            for (int nt2 = 0; nt2 < 4; nt2++) {
                uint32_t bh[4];
                ldm4(bh, sEh + bRow0 + nt2 * 2048 + gselB);
                #pragma unroll
                for (int mt = 0; mt < 2; mt++) {
                    mma16816(c[mt][2 * nt2],     ah[mt], &bh[0]);
                    mma16816(c[mt][2 * nt2 + 1], ah[mt], &bh[2]);
                    mma16816(c[mt][2 * nt2],     al[mt], &bh[0]);
                    mma16816(c[mt][2 * nt2 + 1], al[mt], &bh[2]);
                }
            }
        }

        // branchless sorted top-3 insert: dist = e2 - 2*cross
        const float* e2s = (const float*)(smem + SM_E2 + (s & 1) * 512);
        #pragma unroll
        for (int nt = 0; nt < 8; nt++) {
            int col = wn * 64 + nt * 8 + tg * 2;
            float2 e2v = *(const float2*)(e2s + col);
            uint32_t kg = (uint32_t)(s * 128 + col);
            #pragma unroll
            for (int mt = 0; mt < 2; mt++)
                #pragma unroll
                for (int h = 0; h < 2; h++) {
                    int q = mt * 2 + h;
                    float k0f = pkkey(fmaf(-2.f, c[mt][nt][h * 2],     e2v.x), kg);
                    float k1f = pkkey(fmaf(-2.f, c[mt][nt][h * 2 + 1], e2v.y), kg + 1);
                    float u, v;
                    u = fmaxf(tv1[q], k0f); tv1[q] = fminf(tv1[q], k0f);
                    v = fmaxf(tv2[q], u);   tv2[q] = fminf(tv2[q], u);
                    tv3[q] = fminf(tv3[q], v);
                    u = fmaxf(tv1[q], k1f); tv1[q] = fminf(tv1[q], k1f);
                    v = fmaxf(tv2[q], u);   tv2[q] = fminf(tv2[q], u);
                    tv3[q] = fminf(tv3[q], v);
                }
        }
    }

    // quad merge over tg lanes (sorted-triple merge), stash per (row, wn)
    #pragma unroll
    for (int q = 0; q < 4; q++) {
        #pragma unroll
        for (int off = 1; off <= 2; off <<= 1) {
            float o1 = __shfl_xor_sync(0xffffffffu, tv1[q], off);
            float o2 = __shfl_xor_sync(0xffffffffu, tv2[q], off);
            float o3 = __shfl_xor_sync(0xffffffffu, tv3[q], off);
            float n1 = fminf(tv1[q], o1);
            float n2 = fminf(fmaxf(tv1[q], o1), fminf(tv2[q], o2));
            float n3 = fminf(fminf(tv3[q], o3),
                             fminf(fmaxf(tv2[q], o1), fmaxf(tv1[q], o2)));
            tv1[q] = n1; tv2[q] = n2; tv3[q] = n3;
        }
        if (tg == 0) {
            int mt = q >> 1, h = q & 1;
            int row = wm * 32 + mt * 16 + h * 8 + g;
            ((float4*)(smem + SM_MG))[row * 2 + wn] =
                make_float4(tv1[q], tv2[q], tv3[q], 0.f);
        }
    }
    __syncthreads();

    // exact fp32 recheck of top-3 per row
    int* bk = (int*)(smem + SM_BK);
    if (tid < 128) {
        const float4* mg = (const float4*)(smem + SM_MG);
        float4 a = mg[tid * 2], b = mg[tid * 2 + 1];
        float m1 = fminf(a.x, b.x);
        float m2 = fminf(fmaxf(a.x, b.x), fminf(a.y, b.y));
        float m3 = fminf(fminf(a.z, b.z), fminf(fmaxf(a.y, b.x), fmaxf(a.x, b.y)));
        int ia = (int)(__float_as_uint(m1) & 1023u);
        int ib = (int)(__float_as_uint(m2) & 1023u);
        int ic = (int)(__float_as_uint(m3) & 1023u);
        const float4* zp = (const float4*)(z + (size_t)(b0 + tid) * LDIM + n * SDIM);
        const float4* ea = (const float4*)(emb + ((size_t)(n * KCODE + ia)) * SDIM);
        const float4* eb = (const float4*)(emb + ((size_t)(n * KCODE + ib)) * SDIM);
        const float4* ec = (const float4*)(emb + ((size_t)(n * KCODE + ic)) * SDIM);
        float da = 0.f, db = 0.f, dc = 0.f;
        #pragma unroll
        for (int i = 0; i < 16; i++) {
            float4 zv = zp[i], va = ea[i], vb = eb[i], vc = ec[i];
            da += zv.x * va.x + zv.y * va.y + zv.z * va.z + zv.w * va.w;
            db += zv.x * vb.x + zv.y * vb.y + zv.z * vb.z + zv.w * vb.w;
            dc += zv.x * vc.x + zv.y * vc.y + zv.z * vc.z + zv.w * vc.w;
        }
        float dA = g_e2[n * KCODE + ia] - 2.f * da;
        float dB = g_e2[n * KCODE + ib] - 2.f * db;
        float dC = g_e2[n * KCODE + ic] - 2.f * dc;
        int   kq = ia; float kd = dA;
        if (dB < kd || (dB == kd && ib < kq)) { kd = dB; kq = ib; }
        if (dC < kd || (dC == kd && ic < kq)) { kd = dC; kq = ic; }
        bk[tid] = kq;
        out[(size_t)BDIM * LDIM + 2 + (size_t)(b0 + tid) * NCODE + n] = (float)kq;
    }
    __syncthreads();

    // gather quant + losses + bf16 copies (2 threads per row, 32 d each)
    {
        const int row   = tid >> 1;
        const int dbase = (tid & 1) * 32;
        const int kq    = bk[row];
        const float4* ep4 = (const float4*)(emb + ((size_t)(n * KCODE + kq)) * SDIM + dbase);
        const float4* zp4 = (const float4*)(z + (size_t)(b0 + row) * LDIM + n * SDIM + dbase);
        float4*       op4 = (float4*)(out + (size_t)(b0 + row) * LDIM + n * SDIM + dbase);
        __nv_bfloat162* qb2 = (__nv_bfloat162*)(g_qb + (size_t)(b0 + row) * LDIM + n * SDIM + dbase);
        __nv_bfloat162* zb2 = (__nv_bfloat162*)(g_zb + (size_t)(b0 + row) * LDIM + n * SDIM + dbase);

        float qs = 0.f, zs = 0.f, cs = 0.f;
        #pragma unroll
        for (int i = 0; i < 8; i++) {
            float4 q4 = ep4[i];
            float4 z4 = zp4[i];
            op4[i] = q4;
            qb2[2 * i]     = __floats2bfloat162_rn(q4.x, q4.y);
            qb2[2 * i + 1] = __floats2bfloat162_rn(q4.z, q4.w);
            zb2[2 * i]     = __floats2bfloat162_rn(z4.x, z4.y);
            zb2[2 * i + 1] = __floats2bfloat162_rn(z4.z, z4.w);
            float d0 = q4.x - z4.x, d1 = q4.y - z4.y, d2 = q4.z - z4.z, d3 = q4.w - z4.w;
            qs += q4.x * q4.x + q4.y * q4.y + q4.z * q4.z + q4.w * q4.w;
            zs += z4.x * z4.x + z4.y * z4.y + z4.z * z4.z + z4.w * z4.w;
            cs += d0 * d0 + d1 * d1 + d2 * d2 + d3 * d3;
        }
        qs += __shfl_xor_sync(0xffffffffu, qs, 1);
        zs += __shfl_xor_sync(0xffffffffu, zs, 1);
        if ((tid & 1) == 0) {
            atomicAdd(&g_qsq[b0 + row], qs);
            atomicAdd(&g_zsq[b0 + row], zs);
        }
        #pragma unroll
        for (int o = 16; o; o >>= 1) cs += __shfl_xor_sync(0xffffffffu, cs, o);
        if ((tid & 31) == 0) atomicAdd(&g_commit, cs);
    }
}

// ============================================================
// k3: bf16 mma.sync GEMM (8192x8192x512) + exp + rowsum + diag
//     R10 double-buffered mainloop (measured best).
//     __launch_bounds__(256,2): regs MUST stay <=128 (RF cliff).
// ============================================================
#define KS 64
#define STG_BYTES (128 * 128)
#define SM3_IQ   (4 * STG_BYTES)           // 512 B invq tile
#define SM3_IZ   (4 * STG_BYTES + 512)     // 512 B invz tile
#define SM3_TOT  (4 * STG_BYTES + 1024)

__global__ void __launch_bounds__(256, 2) k3_mma() {
    extern __shared__ __align__(128) char smem[];
    const uint32_t sb = smem_u32(smem);
    const int tid  = threadIdx.x;
    const int lane = tid & 31, wid = tid >> 5;
    const int wm = wid & 3, wn = wid >> 2;
    const int bm0 = blockIdx.y * 128, bn0 = blockIdx.x * 128;
    const __nv_bfloat16* __restrict__ Qb = g_qb;
    const __nv_bfloat16* __restrict__ Zb = g_zb;

    uint32_t sOff[4]; int gRow[4], gJ[4];
    #pragma unroll
    for (int i = 0; i < 4; i++) {
        int idv = tid + i * 256;
        int row = idv >> 3, j = idv & 7;
        gRow[i] = row; gJ[i] = j;
        sOff[i] = row * 128 + ((j ^ (row & 7)) << 4);
    }

    const int rA  = lane & 15;
    const int hiA = lane >> 4;
    const int rB  = (lane & 7) | ((lane & 16) >> 1);
    const int hiB = (lane >> 3) & 1;
    const int swz = lane & 7;
    const uint32_t aRow0 = (uint32_t)(wm * 32 + rA) * 128;
    const uint32_t bRow0 = (uint32_t)(wn * 64 + rB) * 128;

    float c[2][8][4];
    #pragma unroll
    for (int mt = 0; mt < 2; mt++)
        #pragma unroll
        for (int nt = 0; nt < 8; nt++)
            #pragma unroll
            for (int e = 0; e < 4; e++) c[mt][nt][e] = 0.f;

    // fused k2: compute invq (rows) / invz (cols) into smem
    if (tid < 128) {
        float v = g_qsq[bm0 + tid];
        ((float*)(smem + SM3_IQ))[tid] = INV_TAU / fmaxf(sqrtf(v), 1e-12f);
    } else {
        float v = g_zsq[bn0 + tid - 128];
        ((float*)(smem + SM3_IZ))[tid - 128] = 1.f / fmaxf(sqrtf(v), 1e-12f);
    }

    {
        uint32_t sA = sb, sB = sb + STG_BYTES;
        #pragma unroll
        for (int i = 0; i < 4; i++) {
            cp16(sA + sOff[i], Qb + (size_t)(bm0 + gRow[i]) * LDIM + gJ[i] * 8);
            cp16(sB + sOff[i], Zb + (size_t)(bn0 + gRow[i]) * LDIM + gJ[i] * 8);
        }
        cp_commit();
    }

    #pragma unroll
    for (int s = 0; s < 8; s++) {
        if (s < 7) {
            uint32_t sA = sb + ((s + 1) & 1) * (2 * STG_BYTES);
            uint32_t sB = sA + STG_BYTES;
            int kc = (s + 1) * KS;
            #pragma unroll
            for (int i = 0; i < 4; i++) {
                cp16(sA + sOff[i], Qb + (size_t)(bm0 + gRow[i]) * LDIM + kc + gJ[i] * 8);
                cp16(sB + sOff[i], Zb + (size_t)(bn0 + gRow[i]) * LDIM + kc + gJ[i] * 8);
            }
            cp_commit();
            cp_wait1();
        } else {
            cp_wait0();
        }
        __syncthreads();

        const uint32_t sA = sb + (s & 1) * (2 * STG_BYTES);
        const uint32_t sB = sA + STG_BYTES;

        #pragma unroll
        for (int kk = 0; kk < 4; kk++) {
            uint32_t a[2][4];
            #pragma unroll
            for (int mt = 0; mt < 2; mt++)
                ldm4(a[mt], sA + aRow0 + mt * 2048 + ((((kk << 1) | hiA) ^ swz) << 4));
            uint32_t bfr[4][4];
            #pragma unroll
            for (int nt2 = 0; nt2 < 4; nt2++)
                ldm4(bfr[nt2], sB + bRow0 + nt2 * 2048 + ((((kk << 1) | hiB) ^ swz) << 4));
            #pragma unroll
            for (int mt = 0; mt < 2; mt++)
                #pragma unroll
                for (int nt2 = 0; nt2 < 4; nt2++) {
                    mma16816(c[mt][2 * nt2],     a[mt], &bfr[nt2][0]);
                    mma16816(c[mt][2 * nt2 + 1], a[mt], &bfr[nt2][2]);
                }
        }
        __syncthreads();
    }

    const int g = lane >> 2, tg = lane & 3;
    const bool diagblk = (bm0 == bn0);
    const float* iqS = (const float*)(smem + SM3_IQ);
    const float* izS = (const float*)(smem + SM3_IZ);
    int grow[4]; float iq[4], rs[4];
    #pragma unroll
    for (int mt = 0; mt < 2; mt++)
        #pragma unroll
        for (int h = 0; h < 2; h++) {
            int lr = wm * 32 + mt * 16 + h * 8 + g;
            grow[mt * 2 + h] = bm0 + lr;
            iq[mt * 2 + h] = iqS[lr];
            rs[mt * 2 + h] = 0.f;
        }
    #pragma unroll
    for (int nt = 0; nt < 8; nt++) {
        int lcol = wn * 64 + nt * 8 + tg * 2;
        int col  = bn0 + lcol;
        float iz0 = izS[lcol], iz1 = izS[lcol + 1];
        #pragma unroll
        for (int mt = 0; mt < 2; mt++)
            #pragma unroll
            for (int h = 0; h < 2; h++) {
                int q = mt * 2 + h;
                float l0 = c[mt][nt][h * 2 + 0] * iq[q] * iz0;
                float l1 = c[mt][nt][h * 2 + 1] * iq[q] * iz1;
                if (diagblk) {
                    if (grow[q] == col)     g_diag[grow[q]] = l0;
                    if (grow[q] == col + 1) g_diag[grow[q]] = l1;
                }
                rs[q] += __expf(l0 - MSHIFT) + __expf(l1 - MSHIFT);
            }
    }
    #pragma unroll
    for (int q = 0; q < 4; q++) {
        rs[q] += __shfl_xor_sync(0xffffffffu, rs[q], 1);
        rs[q] += __shfl_xor_sync(0xffffffffu, rs[q], 2);
        if (tg == 0) atomicAdd(&g_rowsum[grow[q]], rs[q]);
    }
}

// ============================================================
// k4: contrastive reduction + last-arriver writes scalars
// ============================================================
__global__ void k4_reduce(float* __restrict__ out) {
    int t = blockIdx.x * 256 + threadIdx.x;
    float s = MSHIFT + logf(g_rowsum[t]) - g_diag[t];
    #pragma unroll
    for (int o = 16; o; o >>= 1) s += __shfl_xor_sync(0xffffffffu, s, o);
    if ((threadIdx.x & 31) == 0) {
        atomicAdd(&g_contrast, s);
        __threadfence();
        int v = atomicAdd(&g_done, 1);
        if (v == 255) {                       // 32 blocks x 8 warps
            float con = atomicAdd(&g_contrast, 0.f);
            float com = atomicAdd(&g_commit, 0.f);
            out[(size_t)BDIM * LDIM]     = 2.0f * com / (float)((size_t)BDIM * LDIM);
            out[(size_t)BDIM * LDIM + 1] = con / (float)BDIM;
        }
    }
}

// ============================================================
extern "C" void kernel_launch(void* const* d_in, const int* in_sizes, int n_in,
                              void* d_out, int out_size)
{
    const float* z   = (const float*)d_in[0];
    const float* emb = (const float*)d_in[1];
    float* out = (float*)d_out;

    cudaFuncSetAttribute(k3_mma, cudaFuncAttributeMaxDynamicSharedMemorySize, SM3_TOT);
    cudaFuncSetAttribute(k1_argmin, cudaFuncAttributeMaxDynamicSharedMemorySize, SM_K1);

    k0_init<<<256, 256>>>(emb);
    dim3 g1(BDIM / 128, NCODE);
    k1_argmin<<<g1, 256, SM_K1>>>(z, emb, out);
    dim3 g3(BDIM / 128, BDIM / 128);
    k3_mma<<<g3, 256, SM3_TOT>>>();
    k4_reduce<<<32, 256>>>(out);
}

// round 15
// speedup vs baseline: 1.1980x; 1.0593x over previous
#include <cuda_runtime.h>
#include <cuda_bf16.h>
#include <math.h>
#include <stdint.h>

#define BDIM   8192
#define LDIM   512
#define NCODE  8
#define KCODE  1024
#define SDIM   64
#define INV_TAU 14.285714285714286f
#define MSHIFT  14.285714285714286f

// ---- scratch (device globals; no allocation allowed) ----
__device__ float g_zsq[BDIM];
__device__ float g_qsq[BDIM];
__device__ float g_rowsum[BDIM];
__device__ float g_diag[BDIM];
__device__ float g_e2[NCODE * KCODE];
__device__ float g_commit;
__device__ float g_contrast;
__device__ int   g_done;
__device__ __nv_bfloat16 g_qb[(size_t)BDIM * LDIM];    // quant_z bf16
__device__ __nv_bfloat16 g_zb[(size_t)BDIM * LDIM];    // z bf16
__device__ __nv_bfloat16 g_ebh[NCODE * KCODE * SDIM];  // emb bf16

// ============================================================
// PTX helpers (base ISA: mma.sync / ldmatrix / cp.async)
// ============================================================
__device__ __forceinline__ uint32_t smem_u32(const void* p) {
    uint32_t a;
    asm("{ .reg .u64 t; cvta.to.shared.u64 t, %1; cvt.u32.u64 %0, t; }" : "=r"(a) : "l"(p));
    return a;
}
__device__ __forceinline__ void ldm4(uint32_t* r, uint32_t addr) {
    asm volatile("ldmatrix.sync.aligned.m8n8.x4.shared.b16 {%0,%1,%2,%3}, [%4];"
        : "=r"(r[0]), "=r"(r[1]), "=r"(r[2]), "=r"(r[3]) : "r"(addr));
}
__device__ __forceinline__ void mma16816(float* c, const uint32_t* a, const uint32_t* b) {
    asm volatile("mma.sync.aligned.m16n8k16.row.col.f32.bf16.bf16.f32 "
        "{%0,%1,%2,%3}, {%4,%5,%6,%7}, {%8,%9}, {%0,%1,%2,%3};"
        : "+f"(c[0]), "+f"(c[1]), "+f"(c[2]), "+f"(c[3])
        : "r"(a[0]), "r"(a[1]), "r"(a[2]), "r"(a[3]), "r"(b[0]), "r"(b[1]));
}
__device__ __forceinline__ void cp16(uint32_t saddr, const void* gaddr) {
    asm volatile("cp.async.cg.shared.global [%0], [%1], 16;" :: "r"(saddr), "l"(gaddr));
}
__device__ __forceinline__ void cp_commit() { asm volatile("cp.async.commit_group;" ::: "memory"); }
__device__ __forceinline__ void cp_wait1()  { asm volatile("cp.async.wait_group 1;" ::: "memory"); }
__device__ __forceinline__ void cp_wait0()  { asm volatile("cp.async.wait_group 0;" ::: "memory"); }

__device__ __forceinline__ uint32_t pk(__nv_bfloat16 a, __nv_bfloat16 b) {
    __nv_bfloat162 t; t.x = a; t.y = b;
    return *reinterpret_cast<uint32_t*>(&t);
}
// pack code index into low 10 mantissa bits of distance (approx key)
__device__ __forceinline__ float pkkey(float d, uint32_t kg) {
    return __uint_as_float((__float_as_uint(d) & 0xFFFFFC00u) | kg);
}

// ============================================================
// k0: zero scratch + e2 + bf16 copy of embeddings
// ============================================================
__global__ void k0_init(const float* __restrict__ emb) {
    int t = blockIdx.x * blockDim.x + threadIdx.x;     // 65536 threads
    if (t < BDIM) { g_zsq[t] = 0.f; g_qsq[t] = 0.f; g_rowsum[t] = 0.f; }
    if (t == 0) { g_commit = 0.f; g_contrast = 0.f; g_done = 0; }

    const int code = t >> 3;          // 0..8191
    const int part = t & 7;           // 8 floats each
    const float4* p = (const float4*)(emb + (size_t)code * SDIM + part * 8);
    uint32_t* bh = (uint32_t*)(g_ebh + (size_t)code * SDIM + part * 8);
    float s = 0.f;
    #pragma unroll
    for (int i = 0; i < 2; i++) {
        float4 v = p[i];
        s += v.x * v.x + v.y * v.y + v.z * v.z + v.w * v.w;
        bh[2 * i]     = pk(__float2bfloat16_rn(v.x), __float2bfloat16_rn(v.y));
        bh[2 * i + 1] = pk(__float2bfloat16_rn(v.z), __float2bfloat16_rn(v.w));
    }
    s += __shfl_xor_sync(0xffffffffu, s, 1);
    s += __shfl_xor_sync(0xffffffffu, s, 2);
    s += __shfl_xor_sync(0xffffffffu, s, 4);
    if (part == 0) g_e2[code] = s;
}

// ============================================================
// k1: plain-bf16 MMA argmin (cross ~ zh*eh, dist err sigma ~0.025
//     << top-gap ~8). Branchless sorted top-3 + exact fp32 recheck.
// ============================================================
#define SM_ZH  0
#define SM_EST 16384          // 2 stages x 16384 (Eh only)
#define SM_E2  49152          // 2 stages x 512
#define SM_MG  50176          // 128 rows x 2 warps x 16B
#define SM_BK  54272          // 128 ints
#define SM_K1  54784

__global__ void __launch_bounds__(256, 2) k1_argmin(
    const float* __restrict__ z, const float* __restrict__ emb,
    float* __restrict__ out)
{
    extern __shared__ __align__(128) char smem[];
    const uint32_t sb = smem_u32(smem);
    const int tid  = threadIdx.x;
    const int lane = tid & 31, wid = tid >> 5;
    const int wm = wid & 3, wn = wid >> 2;
    const int b0 = blockIdx.x * 128;
    const int n  = blockIdx.y;

    uint32_t sOff[4]; int gRow[4], gJ[4];
    #pragma unroll
    for (int i = 0; i < 4; i++) {
        int idv = tid + i * 256;
        int row = idv >> 3, j = idv & 7;
        gRow[i] = row; gJ[i] = j;
        sOff[i] = row * 128 + ((j ^ (row & 7)) << 4);
    }
    const __nv_bfloat16* Ebh = g_ebh + (size_t)n * KCODE * SDIM;

    // prologue: stage 0 E tile + e2
    {
        uint32_t sE = sb + SM_EST;
        #pragma unroll
        for (int i = 0; i < 4; i++)
            cp16(sE + sOff[i], Ebh + (size_t)gRow[i] * SDIM + gJ[i] * 8);
        if (tid < 32) cp16(sb + SM_E2 + tid * 16, g_e2 + n * KCODE + tid * 4);
        cp_commit();
    }

    // build Zh smem tile (swizzled) from fp32 z
    #pragma unroll
    for (int i = 0; i < 4; i++) {
        int idv = tid + i * 256;
        int row = idv >> 3, j = idv & 7;
        const float4* zp = (const float4*)(z + (size_t)(b0 + row) * LDIM + n * SDIM + j * 8);
        float4 v0 = zp[0], v1 = zp[1];
        uint32_t hv[4];
        hv[0] = pk(__float2bfloat16_rn(v0.x), __float2bfloat16_rn(v0.y));
        hv[1] = pk(__float2bfloat16_rn(v0.z), __float2bfloat16_rn(v0.w));
        hv[2] = pk(__float2bfloat16_rn(v1.x), __float2bfloat16_rn(v1.y));
        hv[3] = pk(__float2bfloat16_rn(v1.z), __float2bfloat16_rn(v1.w));
        uint32_t off = row * 128 + ((j ^ (row & 7)) << 4);
        *(uint4*)(smem + SM_ZH + off) = make_uint4(hv[0], hv[1], hv[2], hv[3]);
    }

    const int rA  = lane & 15;
    const int hiA = lane >> 4;
    const int rB  = (lane & 7) | ((lane & 16) >> 1);
    const int hiB = (lane >> 3) & 1;
    const int swz = lane & 7;
    const uint32_t aRow0 = (uint32_t)(wm * 32 + rA) * 128;
    const uint32_t bRow0 = (uint32_t)(wn * 64 + rB) * 128;

    // branchless sorted top-3 keys per row slot
    float tv1[4], tv2[4], tv3[4];
    #pragma unroll
    for (int q = 0; q < 4; q++) {
        tv1[q] = __uint_as_float(0x7F800000u);
        tv2[q] = tv1[q]; tv3[q] = tv1[q];
    }

    const int g = lane >> 2, tg = lane & 3;

    #pragma unroll
    for (int s = 0; s < 8; s++) {
        cp_wait0();              // stage s ready (distance-1 prefetch)
        __syncthreads();         // all warps done with stage s-1 buffers
        if (s + 1 < 8) {
            uint32_t sE = sb + SM_EST + ((s + 1) & 1) * 16384;
            size_t base = (size_t)(s + 1) * 128 * SDIM;
            #pragma unroll
            for (int i = 0; i < 4; i++)
                cp16(sE + sOff[i], Ebh + base + (size_t)gRow[i] * SDIM + gJ[i] * 8);
            if (tid < 32)
                cp16(sb + SM_E2 + ((s + 1) & 1) * 512 + tid * 16,
                     g_e2 + n * KCODE + (s + 1) * 128 + tid * 4);
            cp_commit();
        }

        const uint32_t sEh = sb + SM_EST + (s & 1) * 16384;

        float c[2][8][4] = {};
        #pragma unroll
        for (int kk = 0; kk < 4; kk++) {
            const uint32_t gsel  = (((kk << 1) | hiA) ^ swz) << 4;
            const uint32_t gselB = (((kk << 1) | hiB) ^ swz) << 4;
            uint32_t ah[2][4];
            #pragma unroll
            for (int mt = 0; mt < 2; mt++)
                ldm4(ah[mt], sb + SM_ZH + aRow0 + mt * 2048 + gsel);
            #pragma unroll
            for (int nt2 = 0; nt2 < 4; nt2++) {
                uint32_t bh[4];
                ldm4(bh, sEh + bRow0 + nt2 * 2048 + gselB);
                #pragma unroll
                for (int mt = 0; mt < 2; mt++) {
                    mma16816(c[mt][2 * nt2],     ah[mt], &bh[0]);
                    mma16816(c[mt][2 * nt2 + 1], ah[mt], &bh[2]);
                }
            }
        }

        // branchless sorted top-3 insert: dist = e2 - 2*cross
        const float* e2s = (const float*)(smem + SM_E2 + (s & 1) * 512);
        #pragma unroll
        for (int nt = 0; nt < 8; nt++) {
            int col = wn * 64 + nt * 8 + tg * 2;
            float2 e2v = *(const float2*)(e2s + col);
            uint32_t kg = (uint32_t)(s * 128 + col);
            #pragma unroll
            for (int mt = 0; mt < 2; mt++)
                #pragma unroll
                for (int h = 0; h < 2; h++) {
                    int q = mt * 2 + h;
                    float k0f = pkkey(fmaf(-2.f, c[mt][nt][h * 2],     e2v.x), kg);
                    float k1f = pkkey(fmaf(-2.f, c[mt][nt][h * 2 + 1], e2v.y), kg + 1);
                    float u, v;
                    u = fmaxf(tv1[q], k0f); tv1[q] = fminf(tv1[q], k0f);
                    v = fmaxf(tv2[q], u);   tv2[q] = fminf(tv2[q], u);
                    tv3[q] = fminf(tv3[q], v);
                    u = fmaxf(tv1[q], k1f); tv1[q] = fminf(tv1[q], k1f);
                    v = fmaxf(tv2[q], u);   tv2[q] = fminf(tv2[q], u);
                    tv3[q] = fminf(tv3[q], v);
                }
        }
    }

    // quad merge over tg lanes (sorted-triple merge), stash per (row, wn)
    #pragma unroll
    for (int q = 0; q < 4; q++) {
        #pragma unroll
        for (int off = 1; off <= 2; off <<= 1) {
            float o1 = __shfl_xor_sync(0xffffffffu, tv1[q], off);
            float o2 = __shfl_xor_sync(0xffffffffu, tv2[q], off);
            float o3 = __shfl_xor_sync(0xffffffffu, tv3[q], off);
            float n1 = fminf(tv1[q], o1);
            float n2 = fminf(fmaxf(tv1[q], o1), fminf(tv2[q], o2));
            float n3 = fminf(fminf(tv3[q], o3),
                             fminf(fmaxf(tv2[q], o1), fmaxf(tv1[q], o2)));
            tv1[q] = n1; tv2[q] = n2; tv3[q] = n3;
        }
        if (tg == 0) {
            int mt = q >> 1, h = q & 1;
            int row = wm * 32 + mt * 16 + h * 8 + g;
            ((float4*)(smem + SM_MG))[row * 2 + wn] =
                make_float4(tv1[q], tv2[q], tv3[q], 0.f);
        }
    }
    __syncthreads();

    // exact fp32 recheck of top-3 per row
    int* bk = (int*)(smem + SM_BK);
    if (tid < 128) {
        const float4* mg = (const float4*)(smem + SM_MG);
        float4 a = mg[tid * 2], b = mg[tid * 2 + 1];
        float m1 = fminf(a.x, b.x);
        float m2 = fminf(fmaxf(a.x, b.x), fminf(a.y, b.y));
        float m3 = fminf(fminf(a.z, b.z), fminf(fmaxf(a.y, b.x), fmaxf(a.x, b.y)));
        int ia = (int)(__float_as_uint(m1) & 1023u);
        int ib = (int)(__float_as_uint(m2) & 1023u);
        int ic = (int)(__float_as_uint(m3) & 1023u);
        const float4* zp = (const float4*)(z + (size_t)(b0 + tid) * LDIM + n * SDIM);
        const float4* ea = (const float4*)(emb + ((size_t)(n * KCODE + ia)) * SDIM);
        const float4* eb = (const float4*)(emb + ((size_t)(n * KCODE + ib)) * SDIM);
        const float4* ec = (const float4*)(emb + ((size_t)(n * KCODE + ic)) * SDIM);
        float da = 0.f, db = 0.f, dc = 0.f;
        #pragma unroll
        for (int i = 0; i < 16; i++) {
            float4 zv = zp[i], va = ea[i], vb = eb[i], vc = ec[i];
            da += zv.x * va.x + zv.y * va.y + zv.z * va.z + zv.w * va.w;
            db += zv.x * vb.x + zv.y * vb.y + zv.z * vb.z + zv.w * vb.w;
            dc += zv.x * vc.x + zv.y * vc.y + zv.z * vc.z + zv.w * vc.w;
        }
        float dA = g_e2[n * KCODE + ia] - 2.f * da;
        float dB = g_e2[n * KCODE + ib] - 2.f * db;
        float dC = g_e2[n * KCODE + ic] - 2.f * dc;
        int   kq = ia; float kd = dA;
        if (dB < kd || (dB == kd && ib < kq)) { kd = dB; kq = ib; }
        if (dC < kd || (dC == kd && ic < kq)) { kd = dC; kq = ic; }
        bk[tid] = kq;
        out[(size_t)BDIM * LDIM + 2 + (size_t)(b0 + tid) * NCODE + n] = (float)kq;
    }
    __syncthreads();

    // gather quant + losses + bf16 copies (2 threads per row, 32 d each)
    {
        const int row   = tid >> 1;
        const int dbase = (tid & 1) * 32;
        const int kq    = bk[row];
        const float4* ep4 = (const float4*)(emb + ((size_t)(n * KCODE + kq)) * SDIM + dbase);
        const float4* zp4 = (const float4*)(z + (size_t)(b0 + row) * LDIM + n * SDIM + dbase);
        float4*       op4 = (float4*)(out + (size_t)(b0 + row) * LDIM + n * SDIM + dbase);
        __nv_bfloat162* qb2 = (__nv_bfloat162*)(g_qb + (size_t)(b0 + row) * LDIM + n * SDIM + dbase);
        __nv_bfloat162* zb2 = (__nv_bfloat162*)(g_zb + (size_t)(b0 + row) * LDIM + n * SDIM + dbase);

        float qs = 0.f, zs = 0.f, cs = 0.f;
        #pragma unroll
        for (int i = 0; i < 8; i++) {
            float4 q4 = ep4[i];
            float4 z4 = zp4[i];
            op4[i] = q4;
            qb2[2 * i]     = __floats2bfloat162_rn(q4.x, q4.y);
            qb2[2 * i + 1] = __floats2bfloat162_rn(q4.z, q4.w);
            zb2[2 * i]     = __floats2bfloat162_rn(z4.x, z4.y);
            zb2[2 * i + 1] = __floats2bfloat162_rn(z4.z, z4.w);
            float d0 = q4.x - z4.x, d1 = q4.y - z4.y, d2 = q4.z - z4.z, d3 = q4.w - z4.w;
            qs += q4.x * q4.x + q4.y * q4.y + q4.z * q4.z + q4.w * q4.w;
            zs += z4.x * z4.x + z4.y * z4.y + z4.z * z4.z + z4.w * z4.w;
            cs += d0 * d0 + d1 * d1 + d2 * d2 + d3 * d3;
        }
        qs += __shfl_xor_sync(0xffffffffu, qs, 1);
        zs += __shfl_xor_sync(0xffffffffu, zs, 1);
        if ((tid & 1) == 0) {
            atomicAdd(&g_qsq[b0 + row], qs);
            atomicAdd(&g_zsq[b0 + row], zs);
        }
        #pragma unroll
        for (int o = 16; o; o >>= 1) cs += __shfl_xor_sync(0xffffffffu, cs, o);
        if ((tid & 31) == 0) atomicAdd(&g_commit, cs);
    }
}

// ============================================================
// k3: bf16 mma.sync GEMM (8192x8192x512) + exp + rowsum + diag
//     R10 double-buffered mainloop (measured best).
//     __launch_bounds__(256,2): regs MUST stay <=128 (RF cliff).
// ============================================================
#define KS 64
#define STG_BYTES (128 * 128)
#define SM3_IQ   (4 * STG_BYTES)           // 512 B invq tile
#define SM3_IZ   (4 * STG_BYTES + 512)     // 512 B invz tile
#define SM3_TOT  (4 * STG_BYTES + 1024)

__global__ void __launch_bounds__(256, 2) k3_mma() {
    extern __shared__ __align__(128) char smem[];
    const uint32_t sb = smem_u32(smem);
    const int tid  = threadIdx.x;
    const int lane = tid & 31, wid = tid >> 5;
    const int wm = wid & 3, wn = wid >> 2;
    const int bm0 = blockIdx.y * 128, bn0 = blockIdx.x * 128;
    const __nv_bfloat16* __restrict__ Qb = g_qb;
    const __nv_bfloat16* __restrict__ Zb = g_zb;

    uint32_t sOff[4]; int gRow[4], gJ[4];
    #pragma unroll
    for (int i = 0; i < 4; i++) {
        int idv = tid + i * 256;
        int row = idv >> 3, j = idv & 7;
        gRow[i] = row; gJ[i] = j;
        sOff[i] = row * 128 + ((j ^ (row & 7)) << 4);
    }

    const int rA  = lane & 15;
    const int hiA = lane >> 4;
    const int rB  = (lane & 7) | ((lane & 16) >> 1);
    const int hiB = (lane >> 3) & 1;
    const int swz = lane & 7;
    const uint32_t aRow0 = (uint32_t)(wm * 32 + rA) * 128;
    const uint32_t bRow0 = (uint32_t)(wn * 64 + rB) * 128;

    float c[2][8][4];
    #pragma unroll
    for (int mt = 0; mt < 2; mt++)
        #pragma unroll
        for (int nt = 0; nt < 8; nt++)
            #pragma unroll
            for (int e = 0; e < 4; e++) c[mt][nt][e] = 0.f;

    // fused k2: compute invq (rows) / invz (cols) into smem
    if (tid < 128) {
        float v = g_qsq[bm0 + tid];
        ((float*)(smem + SM3_IQ))[tid] = INV_TAU / fmaxf(sqrtf(v), 1e-12f);
    } else {
        float v = g_zsq[bn0 + tid - 128];
        ((float*)(smem + SM3_IZ))[tid - 128] = 1.f / fmaxf(sqrtf(v), 1e-12f);
    }

    {
        uint32_t sA = sb, sB = sb + STG_BYTES;
        #pragma unroll
        for (int i = 0; i < 4; i++) {
            cp16(sA + sOff[i], Qb + (size_t)(bm0 + gRow[i]) * LDIM + gJ[i] * 8);
            cp16(sB + sOff[i], Zb + (size_t)(bn0 + gRow[i]) * LDIM + gJ[i] * 8);
        }
        cp_commit();
    }

    #pragma unroll
    for (int s = 0; s < 8; s++) {
        if (s < 7) {
            uint32_t sA = sb + ((s + 1) & 1) * (2 * STG_BYTES);
            uint32_t sB = sA + STG_BYTES;
            int kc = (s + 1) * KS;
            #pragma unroll
            for (int i = 0; i < 4; i++) {
                cp16(sA + sOff[i], Qb + (size_t)(bm0 + gRow[i]) * LDIM + kc + gJ[i] * 8);
                cp16(sB + sOff[i], Zb + (size_t)(bn0 + gRow[i]) * LDIM + kc + gJ[i] * 8);
            }
            cp_commit();
            cp_wait1();
        } else {
            cp_wait0();
        }
        __syncthreads();

        const uint32_t sA = sb + (s & 1) * (2 * STG_BYTES);
        const uint32_t sB = sA + STG_BYTES;

        #pragma unroll
        for (int kk = 0; kk < 4; kk++) {
            uint32_t a[2][4];
            #pragma unroll
            for (int mt = 0; mt < 2; mt++)
                ldm4(a[mt], sA + aRow0 + mt * 2048 + ((((kk << 1) | hiA) ^ swz) << 4));
            uint32_t bfr[4][4];
            #pragma unroll
            for (int nt2 = 0; nt2 < 4; nt2++)
                ldm4(bfr[nt2], sB + bRow0 + nt2 * 2048 + ((((kk << 1) | hiB) ^ swz) << 4));
            #pragma unroll
            for (int mt = 0; mt < 2; mt++)
                #pragma unroll
                for (int nt2 = 0; nt2 < 4; nt2++) {
                    mma16816(c[mt][2 * nt2],     a[mt], &bfr[nt2][0]);
                    mma16816(c[mt][2 * nt2 + 1], a[mt], &bfr[nt2][2]);
                }
        }
        __syncthreads();
    }

    const int g = lane >> 2, tg = lane & 3;
    const bool diagblk = (bm0 == bn0);
    const float* iqS = (const float*)(smem + SM3_IQ);
    const float* izS = (const float*)(smem + SM3_IZ);
    int grow[4]; float iq[4], rs[4];
    #pragma unroll
    for (int mt = 0; mt < 2; mt++)
        #pragma unroll
        for (int h = 0; h < 2; h++) {
            int lr = wm * 32 + mt * 16 + h * 8 + g;
            grow[mt * 2 + h] = bm0 + lr;
            iq[mt * 2 + h] = iqS[lr];
            rs[mt * 2 + h] = 0.f;
        }
    #pragma unroll
    for (int nt = 0; nt < 8; nt++) {
        int lcol = wn * 64 + nt * 8 + tg * 2;
        int col  = bn0 + lcol;
        float iz0 = izS[lcol], iz1 = izS[lcol + 1];
        #pragma unroll
        for (int mt = 0; mt < 2; mt++)
            #pragma unroll
            for (int h = 0; h < 2; h++) {
                int q = mt * 2 + h;
                float l0 = c[mt][nt][h * 2 + 0] * iq[q] * iz0;
                float l1 = c[mt][nt][h * 2 + 1] * iq[q] * iz1;
                if (diagblk) {
                    if (grow[q] == col)     g_diag[grow[q]] = l0;
                    if (grow[q] == col + 1) g_diag[grow[q]] = l1;
                }
                rs[q] += __expf(l0 - MSHIFT) + __expf(l1 - MSHIFT);
            }
    }
    #pragma unroll
    for (int q = 0; q < 4; q++) {
        rs[q] += __shfl_xor_sync(0xffffffffu, rs[q], 1);
        rs[q] += __shfl_xor_sync(0xffffffffu, rs[q], 2);
        if (tg == 0) atomicAdd(&g_rowsum[grow[q]], rs[q]);
    }
}

// ============================================================
// k4: contrastive reduction + last-arriver writes scalars
// ============================================================
__global__ void k4_reduce(float* __restrict__ out) {
    int t = blockIdx.x * 256 + threadIdx.x;
    float s = MSHIFT + logf(g_rowsum[t]) - g_diag[t];
    #pragma unroll
    for (int o = 16; o; o >>= 1) s += __shfl_xor_sync(0xffffffffu, s, o);
    if ((threadIdx.x & 31) == 0) {
        atomicAdd(&g_contrast, s);
        __threadfence();
        int v = atomicAdd(&g_done, 1);
        if (v == 255) {                       // 32 blocks x 8 warps
            float con = atomicAdd(&g_contrast, 0.f);
            float com = atomicAdd(&g_commit, 0.f);
            out[(size_t)BDIM * LDIM]     = 2.0f * com / (float)((size_t)BDIM * LDIM);
            out[(size_t)BDIM * LDIM + 1] = con / (float)BDIM;
        }
    }
}

// ============================================================
extern "C" void kernel_launch(void* const* d_in, const int* in_sizes, int n_in,
                              void* d_out, int out_size)
{
    const float* z   = (const float*)d_in[0];
    const float* emb = (const float*)d_in[1];
    float* out = (float*)d_out;

    cudaFuncSetAttribute(k3_mma, cudaFuncAttributeMaxDynamicSharedMemorySize, SM3_TOT);
    cudaFuncSetAttribute(k1_argmin, cudaFuncAttributeMaxDynamicSharedMemorySize, SM_K1);

    k0_init<<<256, 256>>>(emb);
    dim3 g1(BDIM / 128, NCODE);
    k1_argmin<<<g1, 256, SM_K1>>>(z, emb, out);
    dim3 g3(BDIM / 128, BDIM / 128);
    k3_mma<<<g3, 256, SM3_TOT>>>();
    k4_reduce<<<32, 256>>>(out);
}

// round 16
// speedup vs baseline: 1.2048x; 1.0056x over previous
#include <cuda_runtime.h>
#include <cuda_bf16.h>
#include <math.h>
#include <stdint.h>

#define BDIM   8192
#define LDIM   512
#define NCODE  8
#define KCODE  1024
#define SDIM   64
#define INV_TAU 14.285714285714286f
#define MSHIFT  14.285714285714286f

// ---- scratch (device globals; no allocation allowed) ----
__device__ float g_zsq[BDIM];
__device__ float g_qsq[BDIM];
__device__ float g_rowsum[BDIM];
__device__ float g_diag[BDIM];
__device__ float g_e2[NCODE * KCODE];
__device__ float g_commit;
__device__ float g_contrast;
__device__ int   g_done;
__device__ __nv_bfloat16 g_qb[(size_t)BDIM * LDIM];    // quant_z bf16
__device__ __nv_bfloat16 g_zb[(size_t)BDIM * LDIM];    // z bf16
__device__ __nv_bfloat16 g_ebh[NCODE * KCODE * SDIM];  // emb bf16

// ============================================================
// PTX helpers (base ISA: mma.sync / ldmatrix / cp.async)
// ============================================================
__device__ __forceinline__ uint32_t smem_u32(const void* p) {
    uint32_t a;
    asm("{ .reg .u64 t; cvta.to.shared.u64 t, %1; cvt.u32.u64 %0, t; }" : "=r"(a) : "l"(p));
    return a;
}
__device__ __forceinline__ void ldm4(uint32_t* r, uint32_t addr) {
    asm volatile("ldmatrix.sync.aligned.m8n8.x4.shared.b16 {%0,%1,%2,%3}, [%4];"
        : "=r"(r[0]), "=r"(r[1]), "=r"(r[2]), "=r"(r[3]) : "r"(addr));
}
__device__ __forceinline__ void mma16816(float* c, const uint32_t* a, const uint32_t* b) {
    asm volatile("mma.sync.aligned.m16n8k16.row.col.f32.bf16.bf16.f32 "
        "{%0,%1,%2,%3}, {%4,%5,%6,%7}, {%8,%9}, {%0,%1,%2,%3};"
        : "+f"(c[0]), "+f"(c[1]), "+f"(c[2]), "+f"(c[3])
        : "r"(a[0]), "r"(a[1]), "r"(a[2]), "r"(a[3]), "r"(b[0]), "r"(b[1]));
}
__device__ __forceinline__ void cp16(uint32_t saddr, const void* gaddr) {
    asm volatile("cp.async.cg.shared.global [%0], [%1], 16;" :: "r"(saddr), "l"(gaddr));
}
__device__ __forceinline__ void cp_commit() { asm volatile("cp.async.commit_group;" ::: "memory"); }
__device__ __forceinline__ void cp_wait0()  { asm volatile("cp.async.wait_group 0;" ::: "memory"); }

__device__ __forceinline__ uint32_t pk(__nv_bfloat16 a, __nv_bfloat16 b) {
    __nv_bfloat162 t; t.x = a; t.y = b;
    return *reinterpret_cast<uint32_t*>(&t);
}
// pack code index into low 10 mantissa bits of distance (approx key)
__device__ __forceinline__ float pkkey(float d, uint32_t kg) {
    return __uint_as_float((__float_as_uint(d) & 0xFFFFFC00u) | kg);
}

// ============================================================
// k0: zero scratch + e2 + bf16 copy of embeddings
// ============================================================
__global__ void k0_init(const float* __restrict__ emb) {
    int t = blockIdx.x * blockDim.x + threadIdx.x;     // 65536 threads
    if (t < BDIM) { g_zsq[t] = 0.f; g_qsq[t] = 0.f; g_rowsum[t] = 0.f; }
    if (t == 0) { g_commit = 0.f; g_contrast = 0.f; g_done = 0; }

    const int code = t >> 3;          // 0..8191
    const int part = t & 7;           // 8 floats each
    const float4* p = (const float4*)(emb + (size_t)code * SDIM + part * 8);
    uint32_t* bh = (uint32_t*)(g_ebh + (size_t)code * SDIM + part * 8);
    float s = 0.f;
    #pragma unroll
    for (int i = 0; i < 2; i++) {
        float4 v = p[i];
        s += v.x * v.x + v.y * v.y + v.z * v.z + v.w * v.w;
        bh[2 * i]     = pk(__float2bfloat16_rn(v.x), __float2bfloat16_rn(v.y));
        bh[2 * i + 1] = pk(__float2bfloat16_rn(v.z), __float2bfloat16_rn(v.w));
    }
    s += __shfl_xor_sync(0xffffffffu, s, 1);
    s += __shfl_xor_sync(0xffffffffu, s, 2);
    s += __shfl_xor_sync(0xffffffffu, s, 4);
    if (part == 0) g_e2[code] = s;
}

// ============================================================
// k1: plain-bf16 MMA argmin (cross ~ zh*eh, dist err sigma ~0.025
//     << top-gap ~8). Branchless sorted top-3 + exact fp32 recheck.
// ============================================================
#define SM_ZH  0
#define SM_EST 16384          // 2 stages x 16384 (Eh only)
#define SM_E2  49152          // 2 stages x 512
#define SM_MG  50176          // 128 rows x 2 warps x 16B
#define SM_BK  54272          // 128 ints
#define SM_K1  54784

__global__ void __launch_bounds__(256, 2) k1_argmin(
    const float* __restrict__ z, const float* __restrict__ emb,
    float* __restrict__ out)
{
    extern __shared__ __align__(128) char smem[];
    const uint32_t sb = smem_u32(smem);
    const int tid  = threadIdx.x;
    const int lane = tid & 31, wid = tid >> 5;
    const int wm = wid & 3, wn = wid >> 2;
    const int b0 = blockIdx.x * 128;
    const int n  = blockIdx.y;

    uint32_t sOff[4]; int gRow[4], gJ[4];
    #pragma unroll
    for (int i = 0; i < 4; i++) {
        int idv = tid + i * 256;
        int row = idv >> 3, j = idv & 7;
        gRow[i] = row; gJ[i] = j;
        sOff[i] = row * 128 + ((j ^ (row & 7)) << 4);
    }
    const __nv_bfloat16* Ebh = g_ebh + (size_t)n * KCODE * SDIM;

    // prologue: stage 0 E tile + e2
    {
        uint32_t sE = sb + SM_EST;
        #pragma unroll
        for (int i = 0; i < 4; i++)
            cp16(sE + sOff[i], Ebh + (size_t)gRow[i] * SDIM + gJ[i] * 8);
        if (tid < 32) cp16(sb + SM_E2 + tid * 16, g_e2 + n * KCODE + tid * 4);
        cp_commit();
    }

    // build Zh smem tile (swizzled) from fp32 z
    #pragma unroll
    for (int i = 0; i < 4; i++) {
        int idv = tid + i * 256;
        int row = idv >> 3, j = idv & 7;
        const float4* zp = (const float4*)(z + (size_t)(b0 + row) * LDIM + n * SDIM + j * 8);
        float4 v0 = zp[0], v1 = zp[1];
        uint32_t hv[4];
        hv[0] = pk(__float2bfloat16_rn(v0.x), __float2bfloat16_rn(v0.y));
        hv[1] = pk(__float2bfloat16_rn(v0.z), __float2bfloat16_rn(v0.w));
        hv[2] = pk(__float2bfloat16_rn(v1.x), __float2bfloat16_rn(v1.y));
        hv[3] = pk(__float2bfloat16_rn(v1.z), __float2bfloat16_rn(v1.w));
        uint32_t off = row * 128 + ((j ^ (row & 7)) << 4);
        *(uint4*)(smem + SM_ZH + off) = make_uint4(hv[0], hv[1], hv[2], hv[3]);
    }

    const int rA  = lane & 15;
    const int hiA = lane >> 4;
    const int rB  = (lane & 7) | ((lane & 16) >> 1);
    const int hiB = (lane >> 3) & 1;
    const int swz = lane & 7;
    const uint32_t aRow0 = (uint32_t)(wm * 32 + rA) * 128;
    const uint32_t bRow0 = (uint32_t)(wn * 64 + rB) * 128;

    // branchless sorted top-3 keys per row slot
    float tv1[4], tv2[4], tv3[4];
    #pragma unroll
    for (int q = 0; q < 4; q++) {
        tv1[q] = __uint_as_float(0x7F800000u);
        tv2[q] = tv1[q]; tv3[q] = tv1[q];
    }

    const int g = lane >> 2, tg = lane & 3;

    #pragma unroll
    for (int s = 0; s < 8; s++) {
        cp_wait0();              // stage s ready (distance-1 prefetch)
        __syncthreads();         // all warps done with stage s-1 buffers
        if (s + 1 < 8) {
            uint32_t sE = sb + SM_EST + ((s + 1) & 1) * 16384;
            size_t base = (size_t)(s + 1) * 128 * SDIM;
            #pragma unroll
            for (int i = 0; i < 4; i++)
                cp16(sE + sOff[i], Ebh + base + (size_t)gRow[i] * SDIM + gJ[i] * 8);
            if (tid < 32)
                cp16(sb + SM_E2 + ((s + 1) & 1) * 512 + tid * 16,
                     g_e2 + n * KCODE + (s + 1) * 128 + tid * 4);
            cp_commit();
        }

        const uint32_t sEh = sb + SM_EST + (s & 1) * 16384;

        float c[2][8][4] = {};
        #pragma unroll
        for (int kk = 0; kk < 4; kk++) {
            const uint32_t gsel  = (((kk << 1) | hiA) ^ swz) << 4;
            const uint32_t gselB = (((kk << 1) | hiB) ^ swz) << 4;
            uint32_t ah[2][4];
            #pragma unroll
            for (int mt = 0; mt < 2; mt++)
                ldm4(ah[mt], sb + SM_ZH + aRow0 + mt * 2048 + gsel);
            #pragma unroll
            for (int nt2 = 0; nt2 < 4; nt2++) {
                uint32_t bh[4];
                ldm4(bh, sEh + bRow0 + nt2 * 2048 + gselB);
                #pragma unroll
                for (int mt = 0; mt < 2; mt++) {
                    mma16816(c[mt][2 * nt2],     ah[mt], &bh[0]);
                    mma16816(c[mt][2 * nt2 + 1], ah[mt], &bh[2]);
                }
            }
        }

        // branchless sorted top-3 insert: dist = e2 - 2*cross
        const float* e2s = (const float*)(smem + SM_E2 + (s & 1) * 512);
        #pragma unroll
        for (int nt = 0; nt < 8; nt++) {
            int col = wn * 64 + nt * 8 + tg * 2;
            float2 e2v = *(const float2*)(e2s + col);
            uint32_t kg = (uint32_t)(s * 128 + col);
            #pragma unroll
            for (int mt = 0; mt < 2; mt++)
                #pragma unroll
                for (int h = 0; h < 2; h++) {
                    int q = mt * 2 + h;
                    float k0f = pkkey(fmaf(-2.f, c[mt][nt][h * 2],     e2v.x), kg);
                    float k1f = pkkey(fmaf(-2.f, c[mt][nt][h * 2 + 1], e2v.y), kg + 1);
                    float u, v;
                    u = fmaxf(tv1[q], k0f); tv1[q] = fminf(tv1[q], k0f);
                    v = fmaxf(tv2[q], u);   tv2[q] = fminf(tv2[q], u);
                    tv3[q] = fminf(tv3[q], v);
                    u = fmaxf(tv1[q], k1f); tv1[q] = fminf(tv1[q], k1f);
                    v = fmaxf(tv2[q], u);   tv2[q] = fminf(tv2[q], u);
                    tv3[q] = fminf(tv3[q], v);
                }
        }
    }

    // quad merge over tg lanes (sorted-triple merge), stash per (row, wn)
    #pragma unroll
    for (int q = 0; q < 4; q++) {
        #pragma unroll
        for (int off = 1; off <= 2; off <<= 1) {
            float o1 = __shfl_xor_sync(0xffffffffu, tv1[q], off);
            float o2 = __shfl_xor_sync(0xffffffffu, tv2[q], off);
            float o3 = __shfl_xor_sync(0xffffffffu, tv3[q], off);
            float n1 = fminf(tv1[q], o1);
            float n2 = fminf(fmaxf(tv1[q], o1), fminf(tv2[q], o2));
            float n3 = fminf(fminf(tv3[q], o3),
                             fminf(fmaxf(tv2[q], o1), fmaxf(tv1[q], o2)));
            tv1[q] = n1; tv2[q] = n2; tv3[q] = n3;
        }
        if (tg == 0) {
            int mt = q >> 1, h = q & 1;
            int row = wm * 32 + mt * 16 + h * 8 + g;
            ((float4*)(smem + SM_MG))[row * 2 + wn] =
                make_float4(tv1[q], tv2[q], tv3[q], 0.f);
        }
    }
    __syncthreads();

    // exact fp32 recheck of top-3 per row
    int* bk = (int*)(smem + SM_BK);
    if (tid < 128) {
        const float4* mg = (const float4*)(smem + SM_MG);
        float4 a = mg[tid * 2], b = mg[tid * 2 + 1];
        float m1 = fminf(a.x, b.x);
        float m2 = fminf(fmaxf(a.x, b.x), fminf(a.y, b.y));
        float m3 = fminf(fminf(a.z, b.z), fminf(fmaxf(a.y, b.x), fmaxf(a.x, b.y)));
        int ia = (int)(__float_as_uint(m1) & 1023u);
        int ib = (int)(__float_as_uint(m2) & 1023u);
        int ic = (int)(__float_as_uint(m3) & 1023u);
        const float4* zp = (const float4*)(z + (size_t)(b0 + tid) * LDIM + n * SDIM);
        const float4* ea = (const float4*)(emb + ((size_t)(n * KCODE + ia)) * SDIM);
        const float4* eb = (const float4*)(emb + ((size_t)(n * KCODE + ib)) * SDIM);
        const float4* ec = (const float4*)(emb + ((size_t)(n * KCODE + ic)) * SDIM);
        float da = 0.f, db = 0.f, dc = 0.f;
        #pragma unroll
        for (int i = 0; i < 16; i++) {
            float4 zv = zp[i], va = ea[i], vb = eb[i], vc = ec[i];
            da += zv.x * va.x + zv.y * va.y + zv.z * va.z + zv.w * va.w;
            db += zv.x * vb.x + zv.y * vb.y + zv.z * vb.z + zv.w * vb.w;
            dc += zv.x * vc.x + zv.y * vc.y + zv.z * vc.z + zv.w * vc.w;
        }
        float dA = g_e2[n * KCODE + ia] - 2.f * da;
        float dB = g_e2[n * KCODE + ib] - 2.f * db;
        float dC = g_e2[n * KCODE + ic] - 2.f * dc;
        int   kq = ia; float kd = dA;
        if (dB < kd || (dB == kd && ib < kq)) { kd = dB; kq = ib; }
        if (dC < kd || (dC == kd && ic < kq)) { kd = dC; kq = ic; }
        bk[tid] = kq;
        out[(size_t)BDIM * LDIM + 2 + (size_t)(b0 + tid) * NCODE + n] = (float)kq;
    }
    __syncthreads();

    // gather quant + losses + bf16 copies (2 threads per row, 32 d each)
    {
        const int row   = tid >> 1;
        const int dbase = (tid & 1) * 32;
        const int kq    = bk[row];
        const float4* ep4 = (const float4*)(emb + ((size_t)(n * KCODE + kq)) * SDIM + dbase);
        const float4* zp4 = (const float4*)(z + (size_t)(b0 + row) * LDIM + n * SDIM + dbase);
        float4*       op4 = (float4*)(out + (size_t)(b0 + row) * LDIM + n * SDIM + dbase);
        __nv_bfloat162* qb2 = (__nv_bfloat162*)(g_qb + (size_t)(b0 + row) * LDIM + n * SDIM + dbase);
        __nv_bfloat162* zb2 = (__nv_bfloat162*)(g_zb + (size_t)(b0 + row) * LDIM + n * SDIM + dbase);

        float qs = 0.f, zs = 0.f, cs = 0.f;
        #pragma unroll
        for (int i = 0; i < 8; i++) {
            float4 q4 = ep4[i];
            float4 z4 = zp4[i];
            op4[i] = q4;
            qb2[2 * i]     = __floats2bfloat162_rn(q4.x, q4.y);
            qb2[2 * i + 1] = __floats2bfloat162_rn(q4.z, q4.w);
            zb2[2 * i]     = __floats2bfloat162_rn(z4.x, z4.y);
            zb2[2 * i + 1] = __floats2bfloat162_rn(z4.z, z4.w);
            float d0 = q4.x - z4.x, d1 = q4.y - z4.y, d2 = q4.z - z4.z, d3 = q4.w - z4.w;
            qs += q4.x * q4.x + q4.y * q4.y + q4.z * q4.z + q4.w * q4.w;
            zs += z4.x * z4.x + z4.y * z4.y + z4.z * z4.z + z4.w * z4.w;
            cs += d0 * d0 + d1 * d1 + d2 * d2 + d3 * d3;
        }
        qs += __shfl_xor_sync(0xffffffffu, qs, 1);
        zs += __shfl_xor_sync(0xffffffffu, zs, 1);
        if ((tid & 1) == 0) {
            atomicAdd(&g_qsq[b0 + row], qs);
            atomicAdd(&g_zsq[b0 + row], zs);
        }
        #pragma unroll
        for (int o = 16; o; o >>= 1) cs += __shfl_xor_sync(0xffffffffu, cs, o);
        if ((tid & 31) == 0) atomicAdd(&g_commit, cs);
    }
}

// ============================================================
// k3: bf16 mma.sync GEMM (8192x8192x512) + exp + rowsum + diag
//     Double-buffered, ONE barrier per stage (k1-proven ordering:
//     wait -> sync -> prefetch -> compute; prefetch targets the
//     buffer whose readers all passed the top sync).
//     __launch_bounds__(256,2): regs MUST stay <=128 (RF cliff).
// ============================================================
#define KS 64
#define STG_BYTES (128 * 128)
#define SM3_IQ   (4 * STG_BYTES)           // 512 B invq tile
#define SM3_IZ   (4 * STG_BYTES + 512)     // 512 B invz tile
#define SM3_TOT  (4 * STG_BYTES + 1024)

__global__ void __launch_bounds__(256, 2) k3_mma() {
    extern __shared__ __align__(128) char smem[];
    const uint32_t sb = smem_u32(smem);
    const int tid  = threadIdx.x;
    const int lane = tid & 31, wid = tid >> 5;
    const int wm = wid & 3, wn = wid >> 2;
    const int bm0 = blockIdx.y * 128, bn0 = blockIdx.x * 128;
    const __nv_bfloat16* __restrict__ Qb = g_qb;
    const __nv_bfloat16* __restrict__ Zb = g_zb;

    uint32_t sOff[4]; int gRow[4], gJ[4];
    #pragma unroll
    for (int i = 0; i < 4; i++) {
        int idv = tid + i * 256;
        int row = idv >> 3, j = idv & 7;
        gRow[i] = row; gJ[i] = j;
        sOff[i] = row * 128 + ((j ^ (row & 7)) << 4);
    }

    const int rA  = lane & 15;
    const int hiA = lane >> 4;
    const int rB  = (lane & 7) | ((lane & 16) >> 1);
    const int hiB = (lane >> 3) & 1;
    const int swz = lane & 7;
    const uint32_t aRow0 = (uint32_t)(wm * 32 + rA) * 128;
    const uint32_t bRow0 = (uint32_t)(wn * 64 + rB) * 128;

    float c[2][8][4];
    #pragma unroll
    for (int mt = 0; mt < 2; mt++)
        #pragma unroll
        for (int nt = 0; nt < 8; nt++)
            #pragma unroll
            for (int e = 0; e < 4; e++) c[mt][nt][e] = 0.f;

    // fused k2: compute invq (rows) / invz (cols) into smem
    if (tid < 128) {
        float v = g_qsq[bm0 + tid];
        ((float*)(smem + SM3_IQ))[tid] = INV_TAU / fmaxf(sqrtf(v), 1e-12f);
    } else {
        float v = g_zsq[bn0 + tid - 128];
        ((float*)(smem + SM3_IZ))[tid - 128] = 1.f / fmaxf(sqrtf(v), 1e-12f);
    }

    {
        uint32_t sA = sb, sB = sb + STG_BYTES;
        #pragma unroll
        for (int i = 0; i < 4; i++) {
            cp16(sA + sOff[i], Qb + (size_t)(bm0 + gRow[i]) * LDIM + gJ[i] * 8);
            cp16(sB + sOff[i], Zb + (size_t)(bn0 + gRow[i]) * LDIM + gJ[i] * 8);
        }
        cp_commit();
    }

    #pragma unroll
    for (int s = 0; s < 8; s++) {
        cp_wait0();              // stage s landed (prefetched last iter)
        __syncthreads();         // all warps past stage s-1 buffers
        if (s + 1 < 8) {         // prefetch s+1 into buf (s+1)&1 = (s-1)&1 (safe)
            uint32_t sA = sb + ((s + 1) & 1) * (2 * STG_BYTES);
            uint32_t sB = sA + STG_BYTES;
            int kc = (s + 1) * KS;
            #pragma unroll
            for (int i = 0; i < 4; i++) {
                cp16(sA + sOff[i], Qb + (size_t)(bm0 + gRow[i]) * LDIM + kc + gJ[i] * 8);
                cp16(sB + sOff[i], Zb + (size_t)(bn0 + gRow[i]) * LDIM + kc + gJ[i] * 8);
            }
            cp_commit();
        }

        const uint32_t sA = sb + (s & 1) * (2 * STG_BYTES);
        const uint32_t sB = sA + STG_BYTES;

        #pragma unroll
        for (int kk = 0; kk < 4; kk++) {
            uint32_t a[2][4];
            #pragma unroll
            for (int mt = 0; mt < 2; mt++)
                ldm4(a[mt], sA + aRow0 + mt * 2048 + ((((kk << 1) | hiA) ^ swz) << 4));
            uint32_t bfr[4][4];
            #pragma unroll
            for (int nt2 = 0; nt2 < 4; nt2++)
                ldm4(bfr[nt2], sB + bRow0 + nt2 * 2048 + ((((kk << 1) | hiB) ^ swz) << 4));
            #pragma unroll
            for (int mt = 0; mt < 2; mt++)
                #pragma unroll
                for (int nt2 = 0; nt2 < 4; nt2++) {
                    mma16816(c[mt][2 * nt2],     a[mt], &bfr[nt2][0]);
                    mma16816(c[mt][2 * nt2 + 1], a[mt], &bfr[nt2][2]);
                }
        }
    }

    const int g = lane >> 2, tg = lane & 3;
    const bool diagblk = (bm0 == bn0);
    const float* iqS = (const float*)(smem + SM3_IQ);
    const float* izS = (const float*)(smem + SM3_IZ);
    int grow[4]; float iq[4], rs[4];
    #pragma unroll
    for (int mt = 0; mt < 2; mt++)
        #pragma unroll
        for (int h = 0; h < 2; h++) {
            int lr = wm * 32 + mt * 16 + h * 8 + g;
            grow[mt * 2 + h] = bm0 + lr;
            iq[mt * 2 + h] = iqS[lr];
            rs[mt * 2 + h] = 0.f;
        }
    #pragma unroll
    for (int nt = 0; nt < 8; nt++) {
        int lcol = wn * 64 + nt * 8 + tg * 2;
        int col  = bn0 + lcol;
        float iz0 = izS[lcol], iz1 = izS[lcol + 1];
        #pragma unroll
        for (int mt = 0; mt < 2; mt++)
            #pragma unroll
            for (int h = 0; h < 2; h++) {
                int q = mt * 2 + h;
                float l0 = c[mt][nt][h * 2 + 0] * iq[q] * iz0;
                float l1 = c[mt][nt][h * 2 + 1] * iq[q] * iz1;
                if (diagblk) {
                    if (grow[q] == col)     g_diag[grow[q]] = l0;
                    if (grow[q] == col + 1) g_diag[grow[q]] = l1;
                }
                rs[q] += __expf(l0 - MSHIFT) + __expf(l1 - MSHIFT);
            }
    }
    #pragma unroll
    for (int q = 0; q < 4; q++) {
        rs[q] += __shfl_xor_sync(0xffffffffu, rs[q], 1);
        rs[q] += __shfl_xor_sync(0xffffffffu, rs[q], 2);
        if (tg == 0) atomicAdd(&g_rowsum[grow[q]], rs[q]);
    }
}

// ============================================================
// k4: contrastive reduction + last-arriver writes scalars
// ============================================================
__global__ void k4_reduce(float* __restrict__ out) {
    int t = blockIdx.x * 256 + threadIdx.x;
    float s = MSHIFT + logf(g_rowsum[t]) - g_diag[t];
    #pragma unroll
    for (int o = 16; o; o >>= 1) s += __shfl_xor_sync(0xffffffffu, s, o);
    if ((threadIdx.x & 31) == 0) {
        atomicAdd(&g_contrast, s);
        __threadfence();
        int v = atomicAdd(&g_done, 1);
        if (v == 255) {                       // 32 blocks x 8 warps
            float con = atomicAdd(&g_contrast, 0.f);
            float com = atomicAdd(&g_commit, 0.f);
            out[(size_t)BDIM * LDIM]     = 2.0f * com / (float)((size_t)BDIM * LDIM);
            out[(size_t)BDIM * LDIM + 1] = con / (float)BDIM;
        }
    }
}

// ============================================================
extern "C" void kernel_launch(void* const* d_in, const int* in_sizes, int n_in,
                              void* d_out, int out_size)
{
    const float* z   = (const float*)d_in[0];
    const float* emb = (const float*)d_in[1];
    float* out = (float*)d_out;

    cudaFuncSetAttribute(k3_mma, cudaFuncAttributeMaxDynamicSharedMemorySize, SM3_TOT);
    cudaFuncSetAttribute(k1_argmin, cudaFuncAttributeMaxDynamicSharedMemorySize, SM_K1);

    k0_init<<<256, 256>>>(emb);
    dim3 g1(BDIM / 128, NCODE);
    k1_argmin<<<g1, 256, SM_K1>>>(z, emb, out);
    dim3 g3(BDIM / 128, BDIM / 128);
    k3_mma<<<g3, 256, SM3_TOT>>>();
    k4_reduce<<<32, 256>>>(out);
}